// round 1
// baseline (speedup 1.0000x reference)
#include <cuda_runtime.h>
#include <math.h>

// Problem constants
#define DT   1024     // model dim D
#define FT   4096     // mlp dim F
#define ET   8        // experts
#define TT   8192     // tokens B*S
#define KSEL 2        // experts per token

// GEMM tiling
#define BM 64
#define BN 64
#define BK 16

#define SLOTS  16896          // 16384 assignments + up to 8*(BM-1) padding, rounded
#define MAXT   264            // max padded M-tiles: 16384/64 + 8

// ---------------- device scratch (no runtime allocation allowed) ----------------
__device__ float g_h[(size_t)SLOTS * FT];   // intermediate h  (~277 MB)
__device__ int   g_perm[SLOTS];             // slot -> token (-1 = padding)
__device__ float g_pw[SLOTS];               // slot -> gate weight
__device__ int   g_topk_e[TT * KSEL];
__device__ float g_topk_w[TT * KSEL];
__device__ int   g_counts[ET];
__device__ int   g_cursor[ET];
__device__ int   g_padoff[ET];
__device__ int   g_tile_e[MAXT];
__device__ int   g_tile_r0[MAXT];
__device__ int   g_ntiles;

// ---------------- stage 0: reset ----------------
__global__ void reset_kernel() {
    int i = threadIdx.x;
    if (i < ET) { g_counts[i] = 0; g_cursor[i] = 0; }
}

// ---------------- stage 1: gating (one warp per token) ----------------
__global__ void gate_kernel(const float* __restrict__ x,
                            const float* __restrict__ gw) {
    int gwarp = (blockIdx.x * blockDim.x + threadIdx.x) >> 5;
    int lane  = threadIdx.x & 31;
    if (gwarp >= TT) return;
    const float* xr = x + (size_t)gwarp * DT;

    float acc[ET];
#pragma unroll
    for (int e = 0; e < ET; e++) acc[e] = 0.f;

    for (int i = lane; i < DT; i += 32) {
        float xv = xr[i];
        const float* g = gw + (size_t)i * ET;
#pragma unroll
        for (int e = 0; e < ET; e++) acc[e] += xv * g[e];
    }
#pragma unroll
    for (int e = 0; e < ET; e++) {
#pragma unroll
        for (int o = 16; o; o >>= 1)
            acc[e] += __shfl_xor_sync(0xFFFFFFFFu, acc[e], o);
    }
    if (lane == 0) {
        // top-2 with first-index tie-break (matches jax.lax.top_k)
        int i0 = 0; float v0 = acc[0];
#pragma unroll
        for (int e = 1; e < ET; e++) if (acc[e] > v0) { v0 = acc[e]; i0 = e; }
        int i1 = -1; float v1 = -3.4e38f;
#pragma unroll
        for (int e = 0; e < ET; e++) if (e != i0 && acc[e] > v1) { v1 = acc[e]; i1 = e; }
        // softmax over the two selected (v0 >= v1)
        float e1 = expf(v1 - v0);
        float inv = 1.0f / (1.0f + e1);
        int b = gwarp * KSEL;
        g_topk_e[b]     = i0; g_topk_w[b]     = inv;
        g_topk_e[b + 1] = i1; g_topk_w[b + 1] = e1 * inv;
        atomicAdd(&g_counts[i0], 1);
        atomicAdd(&g_counts[i1], 1);
    }
}

// ---------------- stage 2: plan (padded offsets + tile table) ----------------
__global__ void plan_kernel() {
    if (threadIdx.x != 0 || blockIdx.x != 0) return;
    int off = 0, tile = 0;
    for (int e = 0; e < ET; e++) {
        g_padoff[e] = off;
        int c  = g_counts[e];
        int nt = (c + BM - 1) / BM;
        for (int t = 0; t < nt; t++) {
            g_tile_e[tile]  = e;
            g_tile_r0[tile] = off + t * BM;
            tile++;
        }
        off += nt * BM;
    }
    g_ntiles = tile;
}

// ---------------- stage 3: perm init + scatter ----------------
__global__ void perm_init_kernel() {
    int i = blockIdx.x * blockDim.x + threadIdx.x;
    if (i < SLOTS) g_perm[i] = -1;
}

__global__ void scatter_kernel() {
    int a = blockIdx.x * blockDim.x + threadIdx.x;
    if (a >= TT * KSEL) return;
    int e   = g_topk_e[a];
    int pos = atomicAdd(&g_cursor[e], 1);
    int slot = g_padoff[e] + pos;
    g_perm[slot] = a >> 1;          // token index
    g_pw[slot]   = g_topk_w[a];
}

// ---------------- stage 4: GEMM1  h = silu(x@wi0) * (x@wi1) ----------------
__global__ __launch_bounds__(256, 2)
void gemm1_kernel(const float* __restrict__ x,
                  const float* __restrict__ wi0,
                  const float* __restrict__ wi1) {
    int tile = blockIdx.y;
    if (tile >= g_ntiles) return;
    int e    = g_tile_e[tile];
    int row0 = g_tile_r0[tile];
    int f0   = blockIdx.x * BN;

    __shared__ float As[BK][BM];
    __shared__ float B0s[BK][BN];
    __shared__ float B1s[BK][BN];

    int tid = threadIdx.x;
    int tx  = tid & 15;       // 0..15 -> N
    int ty  = tid >> 4;       // 0..15 -> M

    // A load mapping: 64 rows, 4 threads/row covering k0..k0+15
    int am = tid & 63;
    int ak = (tid >> 6) * 4;
    int tok = g_perm[row0 + am];
    const float* xrow = (tok >= 0) ? (x + (size_t)tok * DT) : nullptr;

    // B load mapping: 16 k-rows x 64 f-cols per stage
    int bk = tid >> 4;
    int bf = (tid & 15) * 4;
    const float* b0p = wi0 + (size_t)e * DT * FT + (size_t)bk * FT + f0 + bf;
    const float* b1p = wi1 + (size_t)e * DT * FT + (size_t)bk * FT + f0 + bf;

    float acc0[4][4] = {}, acc1[4][4] = {};

    for (int k0 = 0; k0 < DT; k0 += BK) {
        float4 av = make_float4(0.f, 0.f, 0.f, 0.f);
        if (xrow) av = *(const float4*)(xrow + k0 + ak);
        As[ak + 0][am] = av.x; As[ak + 1][am] = av.y;
        As[ak + 2][am] = av.z; As[ak + 3][am] = av.w;
        *(float4*)&B0s[bk][bf] = *(const float4*)(b0p + (size_t)k0 * FT);
        *(float4*)&B1s[bk][bf] = *(const float4*)(b1p + (size_t)k0 * FT);
        __syncthreads();
#pragma unroll
        for (int kk = 0; kk < BK; kk++) {
            float4 a4  = *(const float4*)&As[kk][ty * 4];
            float4 b04 = *(const float4*)&B0s[kk][tx * 4];
            float4 b14 = *(const float4*)&B1s[kk][tx * 4];
            float a[4]  = {a4.x, a4.y, a4.z, a4.w};
            float c0[4] = {b04.x, b04.y, b04.z, b04.w};
            float c1[4] = {b14.x, b14.y, b14.z, b14.w};
#pragma unroll
            for (int i = 0; i < 4; i++)
#pragma unroll
                for (int j = 0; j < 4; j++) {
                    acc0[i][j] += a[i] * c0[j];
                    acc1[i][j] += a[i] * c1[j];
                }
        }
        __syncthreads();
    }

#pragma unroll
    for (int i = 0; i < 4; i++) {
        int slot = row0 + ty * 4 + i;
        if (g_perm[slot] < 0) continue;
        float* hp = g_h + (size_t)slot * FT + f0 + tx * 4;
        float4 hv;
        float v;
        v = acc0[i][0]; hv.x = (v / (1.0f + __expf(-v))) * acc1[i][0];
        v = acc0[i][1]; hv.y = (v / (1.0f + __expf(-v))) * acc1[i][1];
        v = acc0[i][2]; hv.z = (v / (1.0f + __expf(-v))) * acc1[i][2];
        v = acc0[i][3]; hv.w = (v / (1.0f + __expf(-v))) * acc1[i][3];
        *(float4*)hp = hv;
    }
}

// ---------------- stage 5: GEMM2  out[t] += w * (h @ wo[e]) ----------------
__global__ __launch_bounds__(256, 2)
void gemm2_kernel(const float* __restrict__ wo, float* __restrict__ out) {
    int tile = blockIdx.y;
    if (tile >= g_ntiles) return;
    int e    = g_tile_e[tile];
    int row0 = g_tile_r0[tile];
    int d0   = blockIdx.x * BN;

    __shared__ float As[BK][BM];
    __shared__ float Bs[BK][BN];

    int tid = threadIdx.x;
    int tx  = tid & 15;
    int ty  = tid >> 4;

    int am = tid & 63;
    int ak = (tid >> 6) * 4;
    int slotA = row0 + am;
    int tokA  = g_perm[slotA];
    const float* arow = (tokA >= 0) ? (g_h + (size_t)slotA * FT) : nullptr;

    int bk = tid >> 4;
    int bf = (tid & 15) * 4;
    const float* bp = wo + (size_t)e * FT * DT + (size_t)bk * DT + d0 + bf;

    float acc[4][4] = {};

    for (int k0 = 0; k0 < FT; k0 += BK) {
        float4 av = make_float4(0.f, 0.f, 0.f, 0.f);
        if (arow) av = *(const float4*)(arow + k0 + ak);
        As[ak + 0][am] = av.x; As[ak + 1][am] = av.y;
        As[ak + 2][am] = av.z; As[ak + 3][am] = av.w;
        *(float4*)&Bs[bk][bf] = *(const float4*)(bp + (size_t)k0 * DT);
        __syncthreads();
#pragma unroll
        for (int kk = 0; kk < BK; kk++) {
            float4 a4 = *(const float4*)&As[kk][ty * 4];
            float4 b4 = *(const float4*)&Bs[kk][tx * 4];
            float a[4] = {a4.x, a4.y, a4.z, a4.w};
            float b[4] = {b4.x, b4.y, b4.z, b4.w};
#pragma unroll
            for (int i = 0; i < 4; i++)
#pragma unroll
                for (int j = 0; j < 4; j++)
                    acc[i][j] += a[i] * b[j];
        }
        __syncthreads();
    }

#pragma unroll
    for (int i = 0; i < 4; i++) {
        int slot = row0 + ty * 4 + i;
        int tok  = g_perm[slot];
        if (tok < 0) continue;
        float w = g_pw[slot];
        float* op = out + (size_t)tok * DT + d0 + tx * 4;
#pragma unroll
        for (int j = 0; j < 4; j++)
            atomicAdd(&op[j], w * acc[i][j]);
    }
}

// ---------------- launch ----------------
extern "C" void kernel_launch(void* const* d_in, const int* in_sizes, int n_in,
                              void* d_out, int out_size) {
    const float* x   = (const float*)d_in[0];
    const float* gw  = (const float*)d_in[1];
    const float* wi0 = (const float*)d_in[2];
    const float* wi1 = (const float*)d_in[3];
    const float* wo  = (const float*)d_in[4];
    float* out = (float*)d_out;

    reset_kernel<<<1, 32>>>();
    gate_kernel<<<TT / 8, 256>>>(x, gw);
    plan_kernel<<<1, 1>>>();
    perm_init_kernel<<<(SLOTS + 255) / 256, 256>>>();
    scatter_kernel<<<(TT * KSEL + 255) / 256, 256>>>();
    cudaMemsetAsync(d_out, 0, (size_t)out_size * sizeof(float), 0);
    gemm1_kernel<<<dim3(FT / BN, MAXT), 256>>>(x, wi0, wi1);
    gemm2_kernel<<<dim3(DT / BN, MAXT), 256>>>(wo, out);
}

// round 3
// speedup vs baseline: 2.4633x; 2.4633x over previous
#include <cuda_runtime.h>
#include <cuda_bf16.h>
#include <stdint.h>
#include <math.h>

// ---------------- problem constants ----------------
#define DT   1024
#define FT   4096
#define ET   8
#define TT   8192
#define KSEL 2

#define BM    128          // M-tile (slots)
#define SLOTS 17408        // 16384 + 8*(BM-1) padding, rounded up
#define MAXT  136          // max M-tiles

// ---------------- GEMM staging ----------------
#define BK        32
#define STG_BYTES 32768     // Ah 8K | Al 8K | Bh 8K | Bl 8K
#define OFF_A_H   0
#define OFF_A_L   8192
#define OFF_B_H   16384
#define OFF_B_L   24576
#define SMEM_SZ   98304     // 3 stages; epilogue reuses as C-staging

// xor swizzle: 16B chunk c (0..3) within 64B row r
#define SWZ(r, c) ((uint32_t)((((c) ^ ((r) & 3) ^ (((r) >> 2) & 3)) << 4)))

// ---------------- device scratch ----------------
__device__ unsigned short g_xah[(size_t)SLOTS * DT];
__device__ unsigned short g_xal[(size_t)SLOTS * DT];
__device__ unsigned short g_hh[(size_t)SLOTS * FT];
__device__ unsigned short g_hl[(size_t)SLOTS * FT];
__device__ unsigned short g_w0h[(size_t)ET * FT * DT], g_w0l[(size_t)ET * FT * DT];
__device__ unsigned short g_w1h[(size_t)ET * FT * DT], g_w1l[(size_t)ET * FT * DT];
__device__ unsigned short g_woh[(size_t)ET * DT * FT], g_wol[(size_t)ET * DT * FT];

__device__ int   g_perm[SLOTS];
__device__ float g_pw[SLOTS];
__device__ int   g_topk_e[TT * KSEL];
__device__ float g_topk_w[TT * KSEL];
__device__ int   g_counts[ET];
__device__ int   g_cursor[ET];
__device__ int   g_padoff[ET];
__device__ int   g_tile_e[MAXT];
__device__ int   g_tile_r0[MAXT];
__device__ int   g_ntiles;

// ---------------- helpers ----------------
__device__ __forceinline__ uint32_t s2u(const void* p) {
    uint32_t a;
    asm("{ .reg .u64 t; cvta.to.shared.u64 t, %1; cvt.u32.u64 %0, t; }" : "=r"(a) : "l"(p));
    return a;
}
__device__ __forceinline__ void cpasync16(uint32_t dst, const void* src) {
    asm volatile("cp.async.cg.shared.global [%0], [%1], 16;" :: "r"(dst), "l"(src));
}
#define CP_COMMIT() asm volatile("cp.async.commit_group;" ::: "memory")
#define CP_WAIT1()  asm volatile("cp.async.wait_group 1;" ::: "memory")
#define CP_WAIT0()  asm volatile("cp.async.wait_group 0;" ::: "memory")

__device__ __forceinline__ void ldsm4(uint32_t* r, uint32_t a) {
    asm volatile("ldmatrix.sync.aligned.m8n8.x4.shared.b16 {%0,%1,%2,%3}, [%4];"
                 : "=r"(r[0]), "=r"(r[1]), "=r"(r[2]), "=r"(r[3]) : "r"(a));
}
__device__ __forceinline__ void mma16816(float* c, const uint32_t* a, const uint32_t* b) {
    asm volatile("mma.sync.aligned.m16n8k16.row.col.f32.bf16.bf16.f32 "
                 "{%0,%1,%2,%3}, {%4,%5,%6,%7}, {%8,%9}, {%0,%1,%2,%3};"
                 : "+f"(c[0]), "+f"(c[1]), "+f"(c[2]), "+f"(c[3])
                 : "r"(a[0]), "r"(a[1]), "r"(a[2]), "r"(a[3]), "r"(b[0]), "r"(b[1]));
}
__device__ __forceinline__ unsigned short f2bf(float f) {
    return __bfloat16_as_ushort(__float2bfloat16(f));
}
__device__ __forceinline__ float bf2f(unsigned short u) {
    return __bfloat162float(__ushort_as_bfloat16(u));
}

// ---------------- stage 0: reset ----------------
__global__ void reset_kernel() {
    int i = threadIdx.x;
    if (i < ET) { g_counts[i] = 0; g_cursor[i] = 0; }
}

// ---------------- stage 1: gating ----------------
__global__ void gate_kernel(const float* __restrict__ x, const float* __restrict__ gw) {
    int gwarp = (blockIdx.x * blockDim.x + threadIdx.x) >> 5;
    int lane = threadIdx.x & 31;
    if (gwarp >= TT) return;
    const float* xr = x + (size_t)gwarp * DT;
    float acc[ET];
#pragma unroll
    for (int e = 0; e < ET; e++) acc[e] = 0.f;
    for (int i = lane; i < DT; i += 32) {
        float xv = xr[i];
        const float* g = gw + (size_t)i * ET;
#pragma unroll
        for (int e = 0; e < ET; e++) acc[e] += xv * g[e];
    }
#pragma unroll
    for (int e = 0; e < ET; e++)
#pragma unroll
        for (int o = 16; o; o >>= 1)
            acc[e] += __shfl_xor_sync(0xFFFFFFFFu, acc[e], o);
    if (lane == 0) {
        int i0 = 0; float v0 = acc[0];
#pragma unroll
        for (int e = 1; e < ET; e++) if (acc[e] > v0) { v0 = acc[e]; i0 = e; }
        int i1 = -1; float v1 = -3.4e38f;
#pragma unroll
        for (int e = 0; e < ET; e++) if (e != i0 && acc[e] > v1) { v1 = acc[e]; i1 = e; }
        float e1 = expf(v1 - v0);
        float inv = 1.0f / (1.0f + e1);
        int b = gwarp * KSEL;
        g_topk_e[b] = i0;     g_topk_w[b] = inv;
        g_topk_e[b + 1] = i1; g_topk_w[b + 1] = e1 * inv;
        atomicAdd(&g_counts[i0], 1);
        atomicAdd(&g_counts[i1], 1);
    }
}

// ---------------- stage 2: plan ----------------
__global__ void plan_kernel() {
    if (threadIdx.x != 0 || blockIdx.x != 0) return;
    int off = 0, tile = 0;
    for (int e = 0; e < ET; e++) {
        g_padoff[e] = off;
        int c = g_counts[e];
        int nt = (c + BM - 1) / BM;
        for (int t = 0; t < nt; t++) {
            g_tile_e[tile] = e;
            g_tile_r0[tile] = off + t * BM;
            tile++;
        }
        off += nt * BM;
    }
    g_ntiles = tile;
}

// ---------------- stage 3: perm init + scatter ----------------
__global__ void perm_init_kernel() {
    int i = blockIdx.x * blockDim.x + threadIdx.x;
    if (i < SLOTS) g_perm[i] = -1;
}
__global__ void scatter_kernel() {
    int a = blockIdx.x * blockDim.x + threadIdx.x;
    if (a >= TT * KSEL) return;
    int e = g_topk_e[a];
    int pos = atomicAdd(&g_cursor[e], 1);
    int slot = g_padoff[e] + pos;
    g_perm[slot] = a >> 1;
    g_pw[slot] = g_topk_w[a];
}

// ---------------- stage 4: gather + bf16-split x ----------------
__global__ void convert_x_kernel(const float* __restrict__ x) {
    int slot = blockIdx.x;
    int t = threadIdx.x;
    int tok = g_perm[slot];
    float4 v = make_float4(0.f, 0.f, 0.f, 0.f);
    if (tok >= 0) v = ((const float4*)(x + (size_t)tok * DT))[t];
    unsigned short h0 = f2bf(v.x), h1 = f2bf(v.y), h2 = f2bf(v.z), h3 = f2bf(v.w);
    unsigned short l0 = f2bf(v.x - bf2f(h0)), l1 = f2bf(v.y - bf2f(h1));
    unsigned short l2 = f2bf(v.z - bf2f(h2)), l3 = f2bf(v.w - bf2f(h3));
    uint2 ph = make_uint2((uint32_t)h0 | ((uint32_t)h1 << 16), (uint32_t)h2 | ((uint32_t)h3 << 16));
    uint2 pl = make_uint2((uint32_t)l0 | ((uint32_t)l1 << 16), (uint32_t)l2 | ((uint32_t)l3 << 16));
    ((uint2*)g_xah)[(size_t)slot * (DT / 4) + t] = ph;
    ((uint2*)g_xal)[(size_t)slot * (DT / 4) + t] = pl;
}

// ---------------- stage 5: transpose + bf16-split weights ----------------
__global__ void tsplit_kernel(const float* __restrict__ src, int which, int R, int C) {
    __shared__ float t[32][33];
    unsigned short *dh, *dl;
    if (which == 0)      { dh = g_w0h; dl = g_w0l; }
    else if (which == 1) { dh = g_w1h; dl = g_w1l; }
    else                 { dh = g_woh; dl = g_wol; }
    int e = blockIdx.z;
    int c0 = blockIdx.x * 32, r0 = blockIdx.y * 32;
    const float* s = src + (size_t)e * R * C;
#pragma unroll
    for (int i = threadIdx.y; i < 32; i += 8)
        t[i][threadIdx.x] = s[(size_t)(r0 + i) * C + c0 + threadIdx.x];
    __syncthreads();
    size_t ob = (size_t)e * R * C;
#pragma unroll
    for (int i = threadIdx.y; i < 32; i += 8) {
        float v = t[threadIdx.x][i];
        unsigned short h = f2bf(v);
        unsigned short l = f2bf(v - bf2f(h));
        size_t o = ob + (size_t)(c0 + i) * R + r0 + threadIdx.x;
        dh[o] = h; dl[o] = l;
    }
}

// ---------------- shared GEMM machinery ----------------
#define ISSUE_STAGE(s) do {                                              \
    uint32_t bb = sb + ((s) % 3) * STG_BYTES;                            \
    size_t ko = (size_t)(s) * 64;                                        \
    _Pragma("unroll")                                                    \
    for (int j = 0; j < 8; j++) cpasync16(bb + dst[j], src[j] + ko);     \
    CP_COMMIT();                                                         \
} while (0)

#define GEMM_MAINLOOP(KS) do {                                           \
    ISSUE_STAGE(0);                                                      \
    ISSUE_STAGE(1);                                                      \
    for (int s = 0; s < (KS); s++) {                                     \
        CP_WAIT1();                                                      \
        __syncthreads();                                                 \
        if (s + 2 < (KS)) ISSUE_STAGE(s + 2);                            \
        uint32_t b = sb + (s % 3) * STG_BYTES;                           \
        _Pragma("unroll")                                                \
        for (int ks = 0; ks < 2; ks++) {                                 \
            uint32_t ah[4][4], al[4][4], bhf[4][2], blf[4][2];           \
            int rr = lane & 15;                                          \
            int ch = 2 * ks + (lane >> 4);                               \
            _Pragma("unroll")                                            \
            for (int mf = 0; mf < 4; mf++) {                             \
                int r = wm * 64 + mf * 16 + rr;                          \
                uint32_t ad = b + r * 64 + SWZ(r, ch);                   \
                ldsm4(ah[mf], ad + OFF_A_H);                             \
                ldsm4(al[mf], ad + OFF_A_L);                             \
            }                                                            \
            _Pragma("unroll")                                            \
            for (int bi = 0; bi < 2; bi++) {                             \
                int r = wn * 32 + bi * 16 + rr;                          \
                uint32_t ad = b + r * 64 + SWZ(r, ch);                   \
                uint32_t t4[4], u4[4];                                   \
                ldsm4(t4, ad + OFF_B_H);                                 \
                ldsm4(u4, ad + OFF_B_L);                                 \
                bhf[bi*2+0][0] = t4[0]; bhf[bi*2+0][1] = t4[2];          \
                bhf[bi*2+1][0] = t4[1]; bhf[bi*2+1][1] = t4[3];          \
                blf[bi*2+0][0] = u4[0]; blf[bi*2+0][1] = u4[2];          \
                blf[bi*2+1][0] = u4[1]; blf[bi*2+1][1] = u4[3];          \
            }                                                            \
            _Pragma("unroll")                                            \
            for (int mf = 0; mf < 4; mf++)                               \
                _Pragma("unroll")                                        \
                for (int nf = 0; nf < 4; nf++) {                         \
                    mma16816(cf[mf][nf], ah[mf], bhf[nf]);               \
                    mma16816(cf[mf][nf], ah[mf], blf[nf]);               \
                    mma16816(cf[mf][nf], al[mf], bhf[nf]);               \
                }                                                        \
        }                                                                \
        __syncthreads();                                                 \
    }                                                                    \
    CP_WAIT0();                                                          \
    __syncthreads();                                                     \
} while (0)

#define STORE_C_SMEM() do {                                              \
    float* Cs = (float*)dynsm;                                           \
    int g = lane >> 2, t4i = lane & 3;                                   \
    _Pragma("unroll")                                                    \
    for (int mf = 0; mf < 4; mf++)                                       \
        _Pragma("unroll")                                                \
        for (int nf = 0; nf < 4; nf++) {                                 \
            int m0 = wm * 64 + mf * 16 + g;                              \
            int n0 = wn * 32 + nf * 8 + 2 * t4i;                         \
            Cs[m0 * 132 + n0]           = cf[mf][nf][0];                 \
            Cs[m0 * 132 + n0 + 1]       = cf[mf][nf][1];                 \
            Cs[(m0 + 8) * 132 + n0]     = cf[mf][nf][2];                 \
            Cs[(m0 + 8) * 132 + n0 + 1] = cf[mf][nf][3];                 \
        }                                                                \
} while (0)

// ---------------- stage 6: GEMM1  h = silu(x@wi0) * (x@wi1) ----------------
__global__ __launch_bounds__(256, 1) void gemm1_kernel() {
    extern __shared__ char dynsm[];
    int tile = blockIdx.y;
    if (tile >= g_ntiles) return;
    int e = g_tile_e[tile];
    int row0 = g_tile_r0[tile];
    int f0 = blockIdx.x * 64;

    int tid = threadIdx.x;
    int lane = tid & 31;
    int wid = tid >> 5;
    int wm = wid >> 2, wn = wid & 3;
    uint32_t sb = s2u(dynsm);

    const char* src[8];
    uint32_t dst[8];
#pragma unroll
    for (int j = 0; j < 8; j++) {
        int id = tid + j * 256;
        int arr = id >> 9;
        int r = (id >> 2) & 127;
        int c = id & 3;
        dst[j] = (uint32_t)(arr * 8192 + r * 64) + SWZ(r, c);
        const unsigned short* p;
        if (arr == 0)      p = g_xah + (size_t)(row0 + r) * DT;
        else if (arr == 1) p = g_xal + (size_t)(row0 + r) * DT;
        else if (arr == 2) p = ((r < 64) ? (g_w0h + (size_t)e * FT * DT + (size_t)(f0 + r) * DT)
                                         : (g_w1h + (size_t)e * FT * DT + (size_t)(f0 + r - 64) * DT));
        else               p = ((r < 64) ? (g_w0l + (size_t)e * FT * DT + (size_t)(f0 + r) * DT)
                                         : (g_w1l + (size_t)e * FT * DT + (size_t)(f0 + r - 64) * DT));
        src[j] = (const char*)(p + c * 8);
    }

    float cf[4][4][4];
#pragma unroll
    for (int a = 0; a < 4; a++)
#pragma unroll
        for (int b2 = 0; b2 < 4; b2++)
#pragma unroll
            for (int c = 0; c < 4; c++) cf[a][b2][c] = 0.f;

    GEMM_MAINLOOP(DT / BK);

    STORE_C_SMEM();
    __syncthreads();

    const float* Cs = (const float*)dynsm;
#pragma unroll
    for (int i = 0; i < 8; i++) {
        int pos = tid + i * 256;
        int m = pos >> 4;
        int f = (pos & 15) * 4;
        unsigned short hhv[4], hlv[4];
#pragma unroll
        for (int u = 0; u < 4; u++) {
            float d0 = Cs[m * 132 + f + u];
            float d1 = Cs[m * 132 + 64 + f + u];
            float h = (d0 / (1.0f + __expf(-d0))) * d1;
            unsigned short hb = f2bf(h);
            hhv[u] = hb;
            hlv[u] = f2bf(h - bf2f(hb));
        }
        uint2 ph = make_uint2((uint32_t)hhv[0] | ((uint32_t)hhv[1] << 16),
                              (uint32_t)hhv[2] | ((uint32_t)hhv[3] << 16));
        uint2 pl = make_uint2((uint32_t)hlv[0] | ((uint32_t)hlv[1] << 16),
                              (uint32_t)hlv[2] | ((uint32_t)hlv[3] << 16));
        size_t o = (size_t)(row0 + m) * FT + f0 + f;
        *(uint2*)(g_hh + o) = ph;
        *(uint2*)(g_hl + o) = pl;
    }
}

// ---------------- stage 7: GEMM2  out[tok] += w * (h @ wo[e]) ----------------
__global__ __launch_bounds__(256, 1) void gemm2_kernel(float* __restrict__ out) {
    extern __shared__ char dynsm[];
    int tile = blockIdx.y;
    if (tile >= g_ntiles) return;
    int e = g_tile_e[tile];
    int row0 = g_tile_r0[tile];
    int d0 = blockIdx.x * 128;

    int tid = threadIdx.x;
    int lane = tid & 31;
    int wid = tid >> 5;
    int wm = wid >> 2, wn = wid & 3;
    uint32_t sb = s2u(dynsm);

    const char* src[8];
    uint32_t dst[8];
#pragma unroll
    for (int j = 0; j < 8; j++) {
        int id = tid + j * 256;
        int arr = id >> 9;
        int r = (id >> 2) & 127;
        int c = id & 3;
        dst[j] = (uint32_t)(arr * 8192 + r * 64) + SWZ(r, c);
        const unsigned short* p;
        if (arr == 0)      p = g_hh + (size_t)(row0 + r) * FT;
        else if (arr == 1) p = g_hl + (size_t)(row0 + r) * FT;
        else if (arr == 2) p = g_woh + (size_t)e * DT * FT + (size_t)(d0 + r) * FT;
        else               p = g_wol + (size_t)e * DT * FT + (size_t)(d0 + r) * FT;
        src[j] = (const char*)(p + c * 8);
    }

    float cf[4][4][4];
#pragma unroll
    for (int a = 0; a < 4; a++)
#pragma unroll
        for (int b2 = 0; b2 < 4; b2++)
#pragma unroll
            for (int c = 0; c < 4; c++) cf[a][b2][c] = 0.f;

    GEMM_MAINLOOP(FT / BK);

    STORE_C_SMEM();

    // stage tok/pw after the C block
    int* stok = (int*)(dynsm + 128 * 132 * 4);
    float* spw = (float*)(dynsm + 128 * 132 * 4 + 512);
    if (tid < 128) {
        stok[tid] = g_perm[row0 + tid];
        spw[tid] = g_pw[row0 + tid];
    }
    __syncthreads();

    const float* Cs = (const float*)dynsm;
#pragma unroll 8
    for (int i = 0; i < 64; i++) {
        int pos = tid + i * 256;
        int n = pos & 127, m = pos >> 7;
        int tok = stok[m];
        if (tok >= 0)
            atomicAdd(out + (size_t)tok * DT + d0 + n, Cs[m * 132 + n] * spw[m]);
    }
}

// ---------------- launch ----------------
extern "C" void kernel_launch(void* const* d_in, const int* in_sizes, int n_in,
                              void* d_out, int out_size) {
    const float* x   = (const float*)d_in[0];
    const float* gw  = (const float*)d_in[1];
    const float* wi0 = (const float*)d_in[2];
    const float* wi1 = (const float*)d_in[3];
    const float* wo  = (const float*)d_in[4];
    float* out = (float*)d_out;

    cudaFuncSetAttribute(gemm1_kernel, cudaFuncAttributeMaxDynamicSharedMemorySize, SMEM_SZ);
    cudaFuncSetAttribute(gemm2_kernel, cudaFuncAttributeMaxDynamicSharedMemorySize, SMEM_SZ);

    reset_kernel<<<1, 32>>>();
    gate_kernel<<<TT / 8, 256>>>(x, gw);
    plan_kernel<<<1, 1>>>();
    perm_init_kernel<<<(SLOTS + 255) / 256, 256>>>();
    scatter_kernel<<<(TT * KSEL + 255) / 256, 256>>>();
    convert_x_kernel<<<SLOTS, 256>>>(x);
    tsplit_kernel<<<dim3(FT / 32, DT / 32, ET), dim3(32, 8)>>>(wi0, 0, DT, FT);
    tsplit_kernel<<<dim3(FT / 32, DT / 32, ET), dim3(32, 8)>>>(wi1, 1, DT, FT);
    tsplit_kernel<<<dim3(DT / 32, FT / 32, ET), dim3(32, 8)>>>(wo, 2, FT, DT);
    cudaMemsetAsync(d_out, 0, (size_t)out_size * sizeof(float), 0);
    gemm1_kernel<<<dim3(FT / 64, MAXT), 256, SMEM_SZ>>>();
    gemm2_kernel<<<dim3(DT / 128, MAXT), 256, SMEM_SZ>>>(out);
}

// round 4
// speedup vs baseline: 2.9671x; 1.2046x over previous
#include <cuda_runtime.h>
#include <cuda_bf16.h>
#include <stdint.h>
#include <math.h>

// ---------------- problem constants ----------------
#define DT   1024
#define FT   4096
#define ET   8
#define TT   8192
#define KSEL 2

#define BM    128
#define SLOTS 17408
#define MAXT  136

// ---------------- GEMM staging ----------------
#define BK        32
#define STG_BYTES 32768     // Ah 8K | Al 8K | Bh 8K | Bl 8K
#define OFF_A_H   0
#define OFF_A_L   8192
#define OFF_B_H   16384
#define OFF_B_L   24576
#define SMEM_SZ   98304

// A swizzle: 16B chunk c (0..3) within 64B row r (k-contig A rows)
#define SWZ(r, c) ((uint32_t)((((c) ^ ((r) & 3) ^ (((r) >> 2) & 3)) << 4)))
// B swizzle: [K][N] rows of 256B (128 n × 2B); chunk = n>>3 (0..15)
#define BSWZ(k, n) ((uint32_t)((k) * 256 + (((((n) >> 3) ^ ((k) & 7))) << 4) + (((n) & 7) * 2)))

// ---------------- device scratch ----------------
__device__ unsigned short g_xah[(size_t)SLOTS * DT];
__device__ unsigned short g_xal[(size_t)SLOTS * DT];
__device__ unsigned short g_hh[(size_t)SLOTS * FT];
__device__ unsigned short g_hl[(size_t)SLOTS * FT];

__device__ int   g_perm[SLOTS];
__device__ float g_pw[SLOTS];
__device__ int   g_topk_e[TT * KSEL];
__device__ float g_topk_w[TT * KSEL];
__device__ int   g_counts[ET];
__device__ int   g_cursor[ET];
__device__ int   g_padoff[ET];
__device__ int   g_tile_e[MAXT];
__device__ int   g_tile_r0[MAXT];
__device__ int   g_ntiles;

// ---------------- helpers ----------------
__device__ __forceinline__ uint32_t s2u(const void* p) {
    uint32_t a;
    asm("{ .reg .u64 t; cvta.to.shared.u64 t, %1; cvt.u32.u64 %0, t; }" : "=r"(a) : "l"(p));
    return a;
}
__device__ __forceinline__ void cpasync16(uint32_t dst, const void* src) {
    asm volatile("cp.async.cg.shared.global [%0], [%1], 16;" :: "r"(dst), "l"(src));
}
#define CP_COMMIT() asm volatile("cp.async.commit_group;" ::: "memory")
#define CP_WAIT1()  asm volatile("cp.async.wait_group 1;" ::: "memory")
#define CP_WAIT0()  asm volatile("cp.async.wait_group 0;" ::: "memory")

__device__ __forceinline__ void ldsm4(uint32_t* r, uint32_t a) {
    asm volatile("ldmatrix.sync.aligned.m8n8.x4.shared.b16 {%0,%1,%2,%3}, [%4];"
                 : "=r"(r[0]), "=r"(r[1]), "=r"(r[2]), "=r"(r[3]) : "r"(a));
}
__device__ __forceinline__ void ldsm4t(uint32_t* r, uint32_t a) {
    asm volatile("ldmatrix.sync.aligned.m8n8.x4.trans.shared.b16 {%0,%1,%2,%3}, [%4];"
                 : "=r"(r[0]), "=r"(r[1]), "=r"(r[2]), "=r"(r[3]) : "r"(a));
}
__device__ __forceinline__ void mma16816(float* c, const uint32_t* a, const uint32_t* b) {
    asm volatile("mma.sync.aligned.m16n8k16.row.col.f32.bf16.bf16.f32 "
                 "{%0,%1,%2,%3}, {%4,%5,%6,%7}, {%8,%9}, {%0,%1,%2,%3};"
                 : "+f"(c[0]), "+f"(c[1]), "+f"(c[2]), "+f"(c[3])
                 : "r"(a[0]), "r"(a[1]), "r"(a[2]), "r"(a[3]), "r"(b[0]), "r"(b[1]));
}
__device__ __forceinline__ void sts64(uint32_t a, uint32_t x, uint32_t y) {
    asm volatile("st.shared.v2.b32 [%0], {%1,%2};" :: "r"(a), "r"(x), "r"(y) : "memory");
}
__device__ __forceinline__ unsigned short f2bf(float f) {
    return __bfloat16_as_ushort(__float2bfloat16(f));
}
__device__ __forceinline__ float bf2f(unsigned short u) {
    return __bfloat162float(__ushort_as_bfloat16(u));
}
// pack (f0 -> lo16, f1 -> hi16), round-to-nearest
__device__ __forceinline__ uint32_t packbf(float f0, float f1) {
    uint32_t d;
    asm("cvt.rn.bf16x2.f32 %0, %1, %2;" : "=r"(d) : "f"(f1), "f"(f0));
    return d;
}
// hi/lo split of 4 floats -> two packed u32 pairs each
__device__ __forceinline__ void split4(const float4 v, uint32_t* hp, uint32_t* lp) {
    hp[0] = packbf(v.x, v.y);
    hp[1] = packbf(v.z, v.w);
    float h0 = __uint_as_float(hp[0] << 16);
    float h1 = __uint_as_float(hp[0] & 0xFFFF0000u);
    float h2 = __uint_as_float(hp[1] << 16);
    float h3 = __uint_as_float(hp[1] & 0xFFFF0000u);
    lp[0] = packbf(v.x - h0, v.y - h1);
    lp[1] = packbf(v.z - h2, v.w - h3);
}

// ---------------- stage 0: init (reset + perm init) ----------------
__global__ void init_kernel() {
    int i = blockIdx.x * blockDim.x + threadIdx.x;
    if (i < SLOTS) g_perm[i] = -1;
    if (i < ET) { g_counts[i] = 0; g_cursor[i] = 0; }
}

// ---------------- stage 1: gating ----------------
__global__ void gate_kernel(const float* __restrict__ x, const float* __restrict__ gw) {
    int gwarp = (blockIdx.x * blockDim.x + threadIdx.x) >> 5;
    int lane = threadIdx.x & 31;
    if (gwarp >= TT) return;
    const float* xr = x + (size_t)gwarp * DT;
    float acc[ET];
#pragma unroll
    for (int e = 0; e < ET; e++) acc[e] = 0.f;
    for (int i = lane; i < DT; i += 32) {
        float xv = xr[i];
        const float* g = gw + (size_t)i * ET;
#pragma unroll
        for (int e = 0; e < ET; e++) acc[e] += xv * g[e];
    }
#pragma unroll
    for (int e = 0; e < ET; e++)
#pragma unroll
        for (int o = 16; o; o >>= 1)
            acc[e] += __shfl_xor_sync(0xFFFFFFFFu, acc[e], o);
    if (lane == 0) {
        int i0 = 0; float v0 = acc[0];
#pragma unroll
        for (int e = 1; e < ET; e++) if (acc[e] > v0) { v0 = acc[e]; i0 = e; }
        int i1 = -1; float v1 = -3.4e38f;
#pragma unroll
        for (int e = 0; e < ET; e++) if (e != i0 && acc[e] > v1) { v1 = acc[e]; i1 = e; }
        float e1 = expf(v1 - v0);
        float inv = 1.0f / (1.0f + e1);
        int b = gwarp * KSEL;
        g_topk_e[b] = i0;     g_topk_w[b] = inv;
        g_topk_e[b + 1] = i1; g_topk_w[b + 1] = e1 * inv;
        atomicAdd(&g_counts[i0], 1);
        atomicAdd(&g_counts[i1], 1);
    }
}

// ---------------- stage 2: plan ----------------
__global__ void plan_kernel() {
    if (threadIdx.x != 0 || blockIdx.x != 0) return;
    int off = 0, tile = 0;
    for (int e = 0; e < ET; e++) {
        g_padoff[e] = off;
        int c = g_counts[e];
        int nt = (c + BM - 1) / BM;
        for (int t = 0; t < nt; t++) {
            g_tile_e[tile] = e;
            g_tile_r0[tile] = off + t * BM;
            tile++;
        }
        off += nt * BM;
    }
    g_ntiles = tile;
}

// ---------------- stage 3: scatter ----------------
__global__ void scatter_kernel() {
    int a = blockIdx.x * blockDim.x + threadIdx.x;
    if (a >= TT * KSEL) return;
    int e = g_topk_e[a];
    int pos = atomicAdd(&g_cursor[e], 1);
    int slot = g_padoff[e] + pos;
    g_perm[slot] = a >> 1;
    g_pw[slot] = g_topk_w[a];
}

// ---------------- stage 4: gather + bf16-split x ----------------
__global__ void convert_x_kernel(const float* __restrict__ x) {
    int slot = blockIdx.x;
    int t = threadIdx.x;
    int tok = g_perm[slot];
    float4 v = make_float4(0.f, 0.f, 0.f, 0.f);
    if (tok >= 0) v = ((const float4*)(x + (size_t)tok * DT))[t];
    uint32_t hp[2], lp[2];
    split4(v, hp, lp);
    ((uint2*)g_xah)[(size_t)slot * (DT / 4) + t] = make_uint2(hp[0], hp[1]);
    ((uint2*)g_xal)[(size_t)slot * (DT / 4) + t] = make_uint2(lp[0], lp[1]);
}

// ---------------- shared GEMM machinery ----------------
#define ISSUE_A(s) do {                                                  \
    uint32_t bb = sb + ((s) % 3) * STG_BYTES;                            \
    size_t ko = (size_t)(s) * 64;                                        \
    _Pragma("unroll")                                                    \
    for (int j = 0; j < 4; j++) cpasync16(bb + dstA[j], srcA[j] + ko);   \
    CP_COMMIT();                                                         \
} while (0)

#define LDG_B(s) do {                                                    \
    _Pragma("unroll")                                                    \
    for (int j = 0; j < 4; j++)                                          \
        br[j] = *(const float4*)(srcB[j] + (size_t)(s) * 32 * bstride);  \
} while (0)

#define STS_B(s) do {                                                    \
    uint32_t bb = sb + ((s) % 3) * STG_BYTES;                            \
    _Pragma("unroll")                                                    \
    for (int j = 0; j < 4; j++) {                                        \
        uint32_t hp[2], lp[2];                                           \
        split4(br[j], hp, lp);                                           \
        uint32_t ad = bb + BSWZ(wid * 4 + j, bn);                        \
        sts64(ad + OFF_B_H, hp[0], hp[1]);                               \
        sts64(ad + OFF_B_L, lp[0], lp[1]);                               \
    }                                                                    \
} while (0)

#define GEMM_MAINLOOP(KS) do {                                           \
    ISSUE_A(0);                                                          \
    ISSUE_A(1);                                                          \
    LDG_B(0);                                                            \
    for (int s = 0; s < (KS); s++) {                                     \
        CP_WAIT1();                                                      \
        STS_B(s);                                                        \
        __syncthreads();                                                 \
        if (s + 1 < (KS)) LDG_B(s + 1);                                  \
        if (s + 2 < (KS)) ISSUE_A(s + 2);                                \
        uint32_t b = sb + (s % 3) * STG_BYTES;                           \
        _Pragma("unroll")                                                \
        for (int ks = 0; ks < 2; ks++) {                                 \
            uint32_t ah[4][4], al[4][4], bhf[4][2], blf[4][2];           \
            int rr = lane & 15;                                          \
            int ch = 2 * ks + (lane >> 4);                               \
            _Pragma("unroll")                                            \
            for (int mf = 0; mf < 4; mf++) {                             \
                int r = wm * 64 + mf * 16 + rr;                          \
                uint32_t ad = b + r * 64 + SWZ(r, ch);                   \
                ldsm4(ah[mf], ad + OFF_A_H);                             \
                ldsm4(al[mf], ad + OFF_A_L);                             \
            }                                                            \
            {                                                            \
                int mat = lane >> 3, li = lane & 7;                      \
                int kk = ks * 16 + ((mat & 1) << 3) + li;                \
                _Pragma("unroll")                                        \
                for (int bi = 0; bi < 2; bi++) {                         \
                    int nn = wn * 32 + bi * 16 + ((mat >> 1) << 3);      \
                    uint32_t ad = b + BSWZ(kk, nn);                      \
                    uint32_t t4[4], u4[4];                               \
                    ldsm4t(t4, ad + OFF_B_H);                            \
                    ldsm4t(u4, ad + OFF_B_L);                            \
                    bhf[bi*2+0][0] = t4[0]; bhf[bi*2+0][1] = t4[1];      \
                    bhf[bi*2+1][0] = t4[2]; bhf[bi*2+1][1] = t4[3];      \
                    blf[bi*2+0][0] = u4[0]; blf[bi*2+0][1] = u4[1];      \
                    blf[bi*2+1][0] = u4[2]; blf[bi*2+1][1] = u4[3];      \
                }                                                        \
            }                                                            \
            _Pragma("unroll")                                            \
            for (int mf = 0; mf < 4; mf++)                               \
                _Pragma("unroll")                                        \
                for (int nf = 0; nf < 4; nf++) {                         \
                    mma16816(cf[mf][nf], ah[mf], bhf[nf]);               \
                    mma16816(cf[mf][nf], ah[mf], blf[nf]);               \
                    mma16816(cf[mf][nf], al[mf], bhf[nf]);               \
                }                                                        \
        }                                                                \
        __syncthreads();                                                 \
    }                                                                    \
    CP_WAIT0();                                                          \
    __syncthreads();                                                     \
} while (0)

#define STORE_C_SMEM() do {                                              \
    float* Cs = (float*)dynsm;                                           \
    int g = lane >> 2, t4i = lane & 3;                                   \
    _Pragma("unroll")                                                    \
    for (int mf = 0; mf < 4; mf++)                                       \
        _Pragma("unroll")                                                \
        for (int nf = 0; nf < 4; nf++) {                                 \
            int m0 = wm * 64 + mf * 16 + g;                              \
            int n0 = wn * 32 + nf * 8 + 2 * t4i;                         \
            Cs[m0 * 132 + n0]           = cf[mf][nf][0];                 \
            Cs[m0 * 132 + n0 + 1]       = cf[mf][nf][1];                 \
            Cs[(m0 + 8) * 132 + n0]     = cf[mf][nf][2];                 \
            Cs[(m0 + 8) * 132 + n0 + 1] = cf[mf][nf][3];                 \
        }                                                                \
} while (0)

// ---------------- stage 5: GEMM1  h = silu(x@wi0) * (x@wi1) ----------------
__global__ __launch_bounds__(256, 1) void gemm1_kernel(
        const float* __restrict__ wi0, const float* __restrict__ wi1) {
    extern __shared__ char dynsm[];
    int tile = blockIdx.y;
    if (tile >= g_ntiles) return;
    int e = g_tile_e[tile];
    int row0 = g_tile_r0[tile];
    int f0 = blockIdx.x * 64;

    int tid = threadIdx.x;
    int lane = tid & 31;
    int wid = tid >> 5;
    int wm = wid >> 2, wn = wid & 3;
    uint32_t sb = s2u(dynsm);

    // A cp.async setup (hi/lo planes of gathered x)
    const char* srcA[4];
    uint32_t dstA[4];
#pragma unroll
    for (int j = 0; j < 4; j++) {
        int id = tid + j * 256;
        int arr = id >> 9;
        int r = (id >> 2) & 127;
        int c = id & 3;
        dstA[j] = (uint32_t)(arr * 8192 + r * 64) + SWZ(r, c);
        const unsigned short* p = (arr == 0) ? (g_xah + (size_t)(row0 + r) * DT)
                                             : (g_xal + (size_t)(row0 + r) * DT);
        srcA[j] = (const char*)(p + c * 8);
    }

    // B direct fp32 setup: 32 k-rows x 128 n (n<64: wi0, n>=64: wi1)
    const int bstride = FT;      // floats per k-row
    int half = lane >> 4;
    int bn = half * 64 + (lane & 15) * 4;
    const float* bbase = (half ? wi1 : wi0) + (size_t)e * DT * FT + f0 + (lane & 15) * 4;
    const float* srcB[4];
#pragma unroll
    for (int j = 0; j < 4; j++)
        srcB[j] = bbase + (size_t)(wid * 4 + j) * FT;
    float4 br[4];

    float cf[4][4][4];
#pragma unroll
    for (int a = 0; a < 4; a++)
#pragma unroll
        for (int b2 = 0; b2 < 4; b2++)
#pragma unroll
            for (int c = 0; c < 4; c++) cf[a][b2][c] = 0.f;

    GEMM_MAINLOOP(DT / BK);

    STORE_C_SMEM();
    __syncthreads();

    const float* Cs = (const float*)dynsm;
#pragma unroll
    for (int i = 0; i < 8; i++) {
        int pos = tid + i * 256;
        int m = pos >> 4;
        int f = (pos & 15) * 4;
        unsigned short hhv[4], hlv[4];
#pragma unroll
        for (int u = 0; u < 4; u++) {
            float d0 = Cs[m * 132 + f + u];
            float d1 = Cs[m * 132 + 64 + f + u];
            float h = (d0 / (1.0f + __expf(-d0))) * d1;
            unsigned short hb = f2bf(h);
            hhv[u] = hb;
            hlv[u] = f2bf(h - bf2f(hb));
        }
        uint2 ph = make_uint2((uint32_t)hhv[0] | ((uint32_t)hhv[1] << 16),
                              (uint32_t)hhv[2] | ((uint32_t)hhv[3] << 16));
        uint2 pl = make_uint2((uint32_t)hlv[0] | ((uint32_t)hlv[1] << 16),
                              (uint32_t)hlv[2] | ((uint32_t)hlv[3] << 16));
        size_t o = (size_t)(row0 + m) * FT + f0 + f;
        *(uint2*)(g_hh + o) = ph;
        *(uint2*)(g_hl + o) = pl;
    }
}

// ---------------- stage 6: GEMM2  out[tok] += w * (h @ wo[e]) ----------------
__global__ __launch_bounds__(256, 1) void gemm2_kernel(
        const float* __restrict__ wo, float* __restrict__ out) {
    extern __shared__ char dynsm[];
    int tile = blockIdx.y;
    if (tile >= g_ntiles) return;
    int e = g_tile_e[tile];
    int row0 = g_tile_r0[tile];
    int d0 = blockIdx.x * 128;

    int tid = threadIdx.x;
    int lane = tid & 31;
    int wid = tid >> 5;
    int wm = wid >> 2, wn = wid & 3;
    uint32_t sb = s2u(dynsm);

    const char* srcA[4];
    uint32_t dstA[4];
#pragma unroll
    for (int j = 0; j < 4; j++) {
        int id = tid + j * 256;
        int arr = id >> 9;
        int r = (id >> 2) & 127;
        int c = id & 3;
        dstA[j] = (uint32_t)(arr * 8192 + r * 64) + SWZ(r, c);
        const unsigned short* p = (arr == 0) ? (g_hh + (size_t)(row0 + r) * FT)
                                             : (g_hl + (size_t)(row0 + r) * FT);
        srcA[j] = (const char*)(p + c * 8);
    }

    // B: wo[e] is [F][D] (k=f rows, d contiguous): 32 k-rows x 128 d
    const int bstride = DT;
    int bn = lane * 4;
    const float* bbase = wo + (size_t)e * FT * DT + d0 + lane * 4;
    const float* srcB[4];
#pragma unroll
    for (int j = 0; j < 4; j++)
        srcB[j] = bbase + (size_t)(wid * 4 + j) * DT;
    float4 br[4];

    float cf[4][4][4];
#pragma unroll
    for (int a = 0; a < 4; a++)
#pragma unroll
        for (int b2 = 0; b2 < 4; b2++)
#pragma unroll
            for (int c = 0; c < 4; c++) cf[a][b2][c] = 0.f;

    GEMM_MAINLOOP(FT / BK);

    STORE_C_SMEM();

    int* stok = (int*)(dynsm + 128 * 132 * 4);
    float* spw = (float*)(dynsm + 128 * 132 * 4 + 512);
    if (tid < 128) {
        stok[tid] = g_perm[row0 + tid];
        spw[tid] = g_pw[row0 + tid];
    }
    __syncthreads();

    const float* Cs = (const float*)dynsm;
#pragma unroll 8
    for (int i = 0; i < 64; i++) {
        int pos = tid + i * 256;
        int n = pos & 127, m = pos >> 7;
        int tok = stok[m];
        if (tok >= 0)
            atomicAdd(out + (size_t)tok * DT + d0 + n, Cs[m * 132 + n] * spw[m]);
    }
}

// ---------------- launch ----------------
extern "C" void kernel_launch(void* const* d_in, const int* in_sizes, int n_in,
                              void* d_out, int out_size) {
    const float* x   = (const float*)d_in[0];
    const float* gw  = (const float*)d_in[1];
    const float* wi0 = (const float*)d_in[2];
    const float* wi1 = (const float*)d_in[3];
    const float* wo  = (const float*)d_in[4];
    float* out = (float*)d_out;

    cudaFuncSetAttribute(gemm1_kernel, cudaFuncAttributeMaxDynamicSharedMemorySize, SMEM_SZ);
    cudaFuncSetAttribute(gemm2_kernel, cudaFuncAttributeMaxDynamicSharedMemorySize, SMEM_SZ);

    init_kernel<<<(SLOTS + 255) / 256, 256>>>();
    gate_kernel<<<TT / 8, 256>>>(x, gw);
    plan_kernel<<<1, 1>>>();
    scatter_kernel<<<(TT * KSEL + 255) / 256, 256>>>();
    convert_x_kernel<<<SLOTS, 256>>>(x);
    cudaMemsetAsync(d_out, 0, (size_t)out_size * sizeof(float), 0);
    gemm1_kernel<<<dim3(FT / 64, MAXT), 256, SMEM_SZ>>>(wi0, wi1);
    gemm2_kernel<<<dim3(DT / 128, MAXT), 256, SMEM_SZ>>>(wo, out);
}

// round 5
// speedup vs baseline: 3.2577x; 1.0979x over previous
#include <cuda_runtime.h>
#include <cuda_bf16.h>
#include <stdint.h>
#include <math.h>

// ---------------- problem constants ----------------
#define DT   1024
#define FT   4096
#define ET   8
#define TT   8192
#define KSEL 2

#define BM    128
#define SLOTS 17408
#define MAXT  136

// ---------------- GEMM staging (BK=64) ----------------
#define BK        64
#define STG_BYTES 65536     // Ah 16K | Al 16K | Bh 16K | Bl 16K
#define OFF_A_H   0
#define OFF_A_L   16384
#define OFF_B_H   32768
#define OFF_B_L   49152
#define SMEM_SZ   196608    // 3 stages

// A swizzle: 16B chunk c (0..7) within 128B row r
#define SWZ(r, c) ((uint32_t)((((c) ^ ((r) & 7))) << 4))
// B swizzle: [K][N] rows of 256B (128 n x 2B); chunk = n>>3 (0..15)
#define BSWZ(k, n) ((uint32_t)((k) * 256 + (((((n) >> 3) ^ ((k) & 7))) << 4) + (((n) & 7) * 2)))

// ---------------- device scratch ----------------
__device__ unsigned short g_xah[(size_t)SLOTS * DT];
__device__ unsigned short g_xal[(size_t)SLOTS * DT];
__device__ unsigned short g_hh[(size_t)SLOTS * FT];
__device__ unsigned short g_hl[(size_t)SLOTS * FT];

__device__ int   g_perm[SLOTS];
__device__ float g_pw[SLOTS];
__device__ int   g_topk_e[TT * KSEL];
__device__ float g_topk_w[TT * KSEL];
__device__ int   g_counts[ET];
__device__ int   g_cursor[ET];
__device__ int   g_padoff[ET];
__device__ int   g_tile_e[MAXT];
__device__ int   g_tile_r0[MAXT];
__device__ int   g_ntiles;

// ---------------- helpers ----------------
__device__ __forceinline__ uint32_t s2u(const void* p) {
    uint32_t a;
    asm("{ .reg .u64 t; cvta.to.shared.u64 t, %1; cvt.u32.u64 %0, t; }" : "=r"(a) : "l"(p));
    return a;
}
__device__ __forceinline__ void cpasync16(uint32_t dst, const void* src) {
    asm volatile("cp.async.cg.shared.global [%0], [%1], 16;" :: "r"(dst), "l"(src));
}
#define CP_COMMIT() asm volatile("cp.async.commit_group;" ::: "memory")
#define CP_WAIT1()  asm volatile("cp.async.wait_group 1;" ::: "memory")
#define CP_WAIT0()  asm volatile("cp.async.wait_group 0;" ::: "memory")

__device__ __forceinline__ void ldsm4(uint32_t* r, uint32_t a) {
    asm volatile("ldmatrix.sync.aligned.m8n8.x4.shared.b16 {%0,%1,%2,%3}, [%4];"
                 : "=r"(r[0]), "=r"(r[1]), "=r"(r[2]), "=r"(r[3]) : "r"(a));
}
__device__ __forceinline__ void ldsm4t(uint32_t* r, uint32_t a) {
    asm volatile("ldmatrix.sync.aligned.m8n8.x4.trans.shared.b16 {%0,%1,%2,%3}, [%4];"
                 : "=r"(r[0]), "=r"(r[1]), "=r"(r[2]), "=r"(r[3]) : "r"(a));
}
__device__ __forceinline__ void mma16816(float* c, const uint32_t* a, const uint32_t* b) {
    asm volatile("mma.sync.aligned.m16n8k16.row.col.f32.bf16.bf16.f32 "
                 "{%0,%1,%2,%3}, {%4,%5,%6,%7}, {%8,%9}, {%0,%1,%2,%3};"
                 : "+f"(c[0]), "+f"(c[1]), "+f"(c[2]), "+f"(c[3])
                 : "r"(a[0]), "r"(a[1]), "r"(a[2]), "r"(a[3]), "r"(b[0]), "r"(b[1]));
}
__device__ __forceinline__ void sts64(uint32_t a, uint32_t x, uint32_t y) {
    asm volatile("st.shared.v2.b32 [%0], {%1,%2};" :: "r"(a), "r"(x), "r"(y) : "memory");
}
__device__ __forceinline__ unsigned short f2bf(float f) {
    return __bfloat16_as_ushort(__float2bfloat16(f));
}
__device__ __forceinline__ float bf2f(unsigned short u) {
    return __bfloat162float(__ushort_as_bfloat16(u));
}
__device__ __forceinline__ uint32_t packbf(float f0, float f1) {
    uint32_t d;
    asm("cvt.rn.bf16x2.f32 %0, %1, %2;" : "=r"(d) : "f"(f1), "f"(f0));
    return d;
}
__device__ __forceinline__ void split4(const float4 v, uint32_t* hp, uint32_t* lp) {
    hp[0] = packbf(v.x, v.y);
    hp[1] = packbf(v.z, v.w);
    float h0 = __uint_as_float(hp[0] << 16);
    float h1 = __uint_as_float(hp[0] & 0xFFFF0000u);
    float h2 = __uint_as_float(hp[1] << 16);
    float h3 = __uint_as_float(hp[1] & 0xFFFF0000u);
    lp[0] = packbf(v.x - h0, v.y - h1);
    lp[1] = packbf(v.z - h2, v.w - h3);
}

// ---------------- stage 0: init ----------------
__global__ void init_kernel() {
    int i = blockIdx.x * blockDim.x + threadIdx.x;
    if (i < SLOTS) g_perm[i] = -1;
    if (i < ET) { g_counts[i] = 0; g_cursor[i] = 0; }
}

// ---------------- stage 1: gating ----------------
__global__ void gate_kernel(const float* __restrict__ x, const float* __restrict__ gw) {
    int gwarp = (blockIdx.x * blockDim.x + threadIdx.x) >> 5;
    int lane = threadIdx.x & 31;
    if (gwarp >= TT) return;
    const float* xr = x + (size_t)gwarp * DT;
    float acc[ET];
#pragma unroll
    for (int e = 0; e < ET; e++) acc[e] = 0.f;
    for (int i = lane; i < DT; i += 32) {
        float xv = xr[i];
        const float* g = gw + (size_t)i * ET;
#pragma unroll
        for (int e = 0; e < ET; e++) acc[e] += xv * g[e];
    }
#pragma unroll
    for (int e = 0; e < ET; e++)
#pragma unroll
        for (int o = 16; o; o >>= 1)
            acc[e] += __shfl_xor_sync(0xFFFFFFFFu, acc[e], o);
    if (lane == 0) {
        int i0 = 0; float v0 = acc[0];
#pragma unroll
        for (int e = 1; e < ET; e++) if (acc[e] > v0) { v0 = acc[e]; i0 = e; }
        int i1 = -1; float v1 = -3.4e38f;
#pragma unroll
        for (int e = 0; e < ET; e++) if (e != i0 && acc[e] > v1) { v1 = acc[e]; i1 = e; }
        float e1 = expf(v1 - v0);
        float inv = 1.0f / (1.0f + e1);
        int b = gwarp * KSEL;
        g_topk_e[b] = i0;     g_topk_w[b] = inv;
        g_topk_e[b + 1] = i1; g_topk_w[b + 1] = e1 * inv;
        atomicAdd(&g_counts[i0], 1);
        atomicAdd(&g_counts[i1], 1);
    }
}

// ---------------- stage 2: plan ----------------
__global__ void plan_kernel() {
    if (threadIdx.x != 0 || blockIdx.x != 0) return;
    int off = 0, tile = 0;
    for (int e = 0; e < ET; e++) {
        g_padoff[e] = off;
        int c = g_counts[e];
        int nt = (c + BM - 1) / BM;
        for (int t = 0; t < nt; t++) {
            g_tile_e[tile] = e;
            g_tile_r0[tile] = off + t * BM;
            tile++;
        }
        off += nt * BM;
    }
    g_ntiles = tile;
}

// ---------------- stage 3: scatter ----------------
__global__ void scatter_kernel() {
    int a = blockIdx.x * blockDim.x + threadIdx.x;
    if (a >= TT * KSEL) return;
    int e = g_topk_e[a];
    int pos = atomicAdd(&g_cursor[e], 1);
    int slot = g_padoff[e] + pos;
    g_perm[slot] = a >> 1;
    g_pw[slot] = g_topk_w[a];
}

// ---------------- stage 4: gather + bf16-split x ----------------
__global__ void convert_x_kernel(const float* __restrict__ x) {
    int slot = blockIdx.x;
    int t = threadIdx.x;
    int tok = g_perm[slot];
    float4 v = make_float4(0.f, 0.f, 0.f, 0.f);
    if (tok >= 0) v = ((const float4*)(x + (size_t)tok * DT))[t];
    uint32_t hp[2], lp[2];
    split4(v, hp, lp);
    ((uint2*)g_xah)[(size_t)slot * (DT / 4) + t] = make_uint2(hp[0], hp[1]);
    ((uint2*)g_xal)[(size_t)slot * (DT / 4) + t] = make_uint2(lp[0], lp[1]);
}

// ---------------- shared GEMM machinery ----------------
// A: 128 rows x 64 bf16 (hi & lo planes): 2048 16B chunks, 8 per thread
#define ISSUE_A(s) do {                                                  \
    uint32_t bb = sb + ((s) % 3) * STG_BYTES;                            \
    size_t ko = (size_t)(s) * 64;                                        \
    _Pragma("unroll")                                                    \
    for (int j = 0; j < 8; j++) cpasync16(bb + dstA[j], srcA[j] + ko * 2); \
    CP_COMMIT();                                                         \
} while (0)

// B: 64 k-rows x 128 n fp32 -> 8 float4 per thread
#define LDG_B(s) do {                                                    \
    _Pragma("unroll")                                                    \
    for (int j = 0; j < 8; j++)                                          \
        br[j] = *(const float4*)(srcB0 + (size_t)j * bstride             \
                                 + (size_t)(s) * 64 * bstride);          \
} while (0)

#define STS_B(s) do {                                                    \
    uint32_t bb = sb + ((s) % 3) * STG_BYTES;                            \
    _Pragma("unroll")                                                    \
    for (int j = 0; j < 8; j++) {                                        \
        uint32_t hp[2], lp[2];                                           \
        split4(br[j], hp, lp);                                           \
        uint32_t ad = bb + BSWZ(wid * 8 + j, bn);                        \
        sts64(ad + OFF_B_H, hp[0], hp[1]);                               \
        sts64(ad + OFF_B_L, lp[0], lp[1]);                               \
    }                                                                    \
} while (0)

#define GEMM_MAINLOOP(KS) do {                                           \
    ISSUE_A(0);                                                          \
    ISSUE_A(1);                                                          \
    LDG_B(0);                                                            \
    for (int s = 0; s < (KS); s++) {                                     \
        CP_WAIT1();                                                      \
        STS_B(s);                                                        \
        __syncthreads();                                                 \
        if (s + 1 < (KS)) LDG_B(s + 1);                                  \
        if (s + 2 < (KS)) ISSUE_A(s + 2);                                \
        uint32_t b = sb + (s % 3) * STG_BYTES;                           \
        _Pragma("unroll")                                                \
        for (int ks = 0; ks < 4; ks++) {                                 \
            uint32_t ah[4][4], al[4][4], bhf[4][2], blf[4][2];           \
            int rr = lane & 15;                                          \
            int ch = 2 * ks + (lane >> 4);                               \
            _Pragma("unroll")                                            \
            for (int mf = 0; mf < 4; mf++) {                             \
                int r = wm * 64 + mf * 16 + rr;                          \
                uint32_t ad = b + r * 128 + SWZ(r, ch);                  \
                ldsm4(ah[mf], ad + OFF_A_H);                             \
                ldsm4(al[mf], ad + OFF_A_L);                             \
            }                                                            \
            {                                                            \
                int mat = lane >> 3, li = lane & 7;                      \
                int kk = ks * 16 + ((mat & 1) << 3) + li;                \
                _Pragma("unroll")                                        \
                for (int bi = 0; bi < 2; bi++) {                         \
                    int nn = wn * 32 + bi * 16 + ((mat >> 1) << 3);      \
                    uint32_t ad = b + BSWZ(kk, nn);                      \
                    uint32_t t4[4], u4[4];                               \
                    ldsm4t(t4, ad + OFF_B_H);                            \
                    ldsm4t(u4, ad + OFF_B_L);                            \
                    bhf[bi*2+0][0] = t4[0]; bhf[bi*2+0][1] = t4[1];      \
                    bhf[bi*2+1][0] = t4[2]; bhf[bi*2+1][1] = t4[3];      \
                    blf[bi*2+0][0] = u4[0]; blf[bi*2+0][1] = u4[1];      \
                    blf[bi*2+1][0] = u4[2]; blf[bi*2+1][1] = u4[3];      \
                }                                                        \
            }                                                            \
            _Pragma("unroll")                                            \
            for (int mf = 0; mf < 4; mf++)                               \
                _Pragma("unroll")                                        \
                for (int nf = 0; nf < 4; nf++) {                         \
                    mma16816(cf[mf][nf], ah[mf], bhf[nf]);               \
                    mma16816(cf[mf][nf], ah[mf], blf[nf]);               \
                    mma16816(cf[mf][nf], al[mf], bhf[nf]);               \
                }                                                        \
        }                                                                \
    }                                                                    \
    CP_WAIT0();                                                          \
    __syncthreads();                                                     \
} while (0)

#define STORE_C_SMEM() do {                                              \
    float* Cs = (float*)dynsm;                                           \
    int g = lane >> 2, t4i = lane & 3;                                   \
    _Pragma("unroll")                                                    \
    for (int mf = 0; mf < 4; mf++)                                       \
        _Pragma("unroll")                                                \
        for (int nf = 0; nf < 4; nf++) {                                 \
            int m0 = wm * 64 + mf * 16 + g;                              \
            int n0 = wn * 32 + nf * 8 + 2 * t4i;                         \
            Cs[m0 * 132 + n0]           = cf[mf][nf][0];                 \
            Cs[m0 * 132 + n0 + 1]       = cf[mf][nf][1];                 \
            Cs[(m0 + 8) * 132 + n0]     = cf[mf][nf][2];                 \
            Cs[(m0 + 8) * 132 + n0 + 1] = cf[mf][nf][3];                 \
        }                                                                \
} while (0)

// ---------------- stage 5: GEMM1  h = silu(x@wi0) * (x@wi1) ----------------
__global__ __launch_bounds__(256, 1) void gemm1_kernel(
        const float* __restrict__ wi0, const float* __restrict__ wi1) {
    extern __shared__ char dynsm[];
    int tile = blockIdx.y;
    if (tile >= g_ntiles) return;
    int e = g_tile_e[tile];
    int row0 = g_tile_r0[tile];
    int f0 = blockIdx.x * 64;

    int tid = threadIdx.x;
    int lane = tid & 31;
    int wid = tid >> 5;
    int wm = wid >> 2, wn = wid & 3;
    uint32_t sb = s2u(dynsm);

    // A cp.async: 2048 chunks of 16B (hi plane 0..1023, lo plane 1024..2047)
    const char* srcA[8];
    uint32_t dstA[8];
#pragma unroll
    for (int j = 0; j < 8; j++) {
        int id = tid + j * 256;
        int arr = id >> 10;
        int r = (id >> 3) & 127;
        int c = id & 7;
        dstA[j] = (uint32_t)(arr * 16384 + r * 128) + SWZ(r, c);
        const unsigned short* p = (arr == 0) ? (g_xah + (size_t)(row0 + r) * DT)
                                             : (g_xal + (size_t)(row0 + r) * DT);
        srcA[j] = (const char*)(p + c * 8);
    }

    // B: 64 k-rows x 128 n fp32 (n<64: wi0, n>=64: wi1)
    const int bstride = FT;
    int half = lane >> 4;
    int bn = half * 64 + (lane & 15) * 4;
    const float* srcB0 = ((half ? wi1 : wi0) + (size_t)e * DT * FT + f0 + (lane & 15) * 4)
                         + (size_t)(wid * 8) * FT;
    float4 br[8];

    float cf[4][4][4];
#pragma unroll
    for (int a = 0; a < 4; a++)
#pragma unroll
        for (int b2 = 0; b2 < 4; b2++)
#pragma unroll
            for (int c = 0; c < 4; c++) cf[a][b2][c] = 0.f;

    GEMM_MAINLOOP(DT / BK);

    STORE_C_SMEM();
    __syncthreads();

    const float* Cs = (const float*)dynsm;
#pragma unroll
    for (int i = 0; i < 8; i++) {
        int pos = tid + i * 256;
        int m = pos >> 4;
        int f = (pos & 15) * 4;
        unsigned short hhv[4], hlv[4];
#pragma unroll
        for (int u = 0; u < 4; u++) {
            float d0 = Cs[m * 132 + f + u];
            float d1 = Cs[m * 132 + 64 + f + u];
            float h = (d0 / (1.0f + __expf(-d0))) * d1;
            unsigned short hb = f2bf(h);
            hhv[u] = hb;
            hlv[u] = f2bf(h - bf2f(hb));
        }
        uint2 ph = make_uint2((uint32_t)hhv[0] | ((uint32_t)hhv[1] << 16),
                              (uint32_t)hhv[2] | ((uint32_t)hhv[3] << 16));
        uint2 pl = make_uint2((uint32_t)hlv[0] | ((uint32_t)hlv[1] << 16),
                              (uint32_t)hlv[2] | ((uint32_t)hlv[3] << 16));
        size_t o = (size_t)(row0 + m) * FT + f0 + f;
        *(uint2*)(g_hh + o) = ph;
        *(uint2*)(g_hl + o) = pl;
    }
}

// ---------------- stage 6: GEMM2  out[tok] += w * (h @ wo[e]) ----------------
__global__ __launch_bounds__(256, 1) void gemm2_kernel(
        const float* __restrict__ wo, float* __restrict__ out) {
    extern __shared__ char dynsm[];
    int tile = blockIdx.y;
    if (tile >= g_ntiles) return;
    int e = g_tile_e[tile];
    int row0 = g_tile_r0[tile];
    int d0 = blockIdx.x * 128;

    int tid = threadIdx.x;
    int lane = tid & 31;
    int wid = tid >> 5;
    int wm = wid >> 2, wn = wid & 3;
    uint32_t sb = s2u(dynsm);

    const char* srcA[8];
    uint32_t dstA[8];
#pragma unroll
    for (int j = 0; j < 8; j++) {
        int id = tid + j * 256;
        int arr = id >> 10;
        int r = (id >> 3) & 127;
        int c = id & 7;
        dstA[j] = (uint32_t)(arr * 16384 + r * 128) + SWZ(r, c);
        const unsigned short* p = (arr == 0) ? (g_hh + (size_t)(row0 + r) * FT)
                                             : (g_hl + (size_t)(row0 + r) * FT);
        srcA[j] = (const char*)(p + c * 8);
    }

    // B: wo[e] is [F][D]: 64 k-rows x 128 d
    const int bstride = DT;
    int bn = lane * 4;
    const float* srcB0 = (wo + (size_t)e * FT * DT + d0 + lane * 4)
                         + (size_t)(wid * 8) * DT;
    float4 br[8];

    float cf[4][4][4];
#pragma unroll
    for (int a = 0; a < 4; a++)
#pragma unroll
        for (int b2 = 0; b2 < 4; b2++)
#pragma unroll
            for (int c = 0; c < 4; c++) cf[a][b2][c] = 0.f;

    GEMM_MAINLOOP(FT / BK);

    STORE_C_SMEM();

    int* stok = (int*)(dynsm + 128 * 132 * 4);
    float* spw = (float*)(dynsm + 128 * 132 * 4 + 512);
    if (tid < 128) {
        stok[tid] = g_perm[row0 + tid];
        spw[tid] = g_pw[row0 + tid];
    }
    __syncthreads();

    const float* Cs = (const float*)dynsm;
#pragma unroll 8
    for (int i = 0; i < 64; i++) {
        int pos = tid + i * 256;
        int n = pos & 127, m = pos >> 7;
        int tok = stok[m];
        if (tok >= 0)
            atomicAdd(out + (size_t)tok * DT + d0 + n, Cs[m * 132 + n] * spw[m]);
    }
}

// ---------------- launch ----------------
extern "C" void kernel_launch(void* const* d_in, const int* in_sizes, int n_in,
                              void* d_out, int out_size) {
    const float* x   = (const float*)d_in[0];
    const float* gw  = (const float*)d_in[1];
    const float* wi0 = (const float*)d_in[2];
    const float* wi1 = (const float*)d_in[3];
    const float* wo  = (const float*)d_in[4];
    float* out = (float*)d_out;

    cudaFuncSetAttribute(gemm1_kernel, cudaFuncAttributeMaxDynamicSharedMemorySize, SMEM_SZ);
    cudaFuncSetAttribute(gemm2_kernel, cudaFuncAttributeMaxDynamicSharedMemorySize, SMEM_SZ);

    init_kernel<<<(SLOTS + 255) / 256, 256>>>();
    gate_kernel<<<TT / 8, 256>>>(x, gw);
    plan_kernel<<<1, 1>>>();
    scatter_kernel<<<(TT * KSEL + 255) / 256, 256>>>();
    convert_x_kernel<<<SLOTS, 256>>>(x);
    cudaMemsetAsync(d_out, 0, (size_t)out_size * sizeof(float), 0);
    gemm1_kernel<<<dim3(FT / 64, MAXT), 256, SMEM_SZ>>>(wi0, wi1);
    gemm2_kernel<<<dim3(DT / 128, MAXT), 256, SMEM_SZ>>>(wo, out);
}

// round 6
// speedup vs baseline: 4.3877x; 1.3469x over previous
#include <cuda_runtime.h>
#include <cuda_fp16.h>
#include <stdint.h>
#include <math.h>

// ---------------- problem constants ----------------
#define DT   1024
#define FT   4096
#define ET   8
#define TT   8192
#define KSEL 2

#define BM    128
#define SLOTS 17408
#define MAXT  136

// ---------------- GEMM staging (BK=64, fp16 2-term) ----------------
#define BK        64
#define STG_BYTES 49152     // Ah 16K | Al 16K | B 16K
#define OFF_A_H   0
#define OFF_A_L   16384
#define OFF_B     32768
#define SMEM_SZ   147456    // 3 stages

// A swizzle: 16B chunk c (0..7) within 128B row r
#define SWZ(r, c) ((uint32_t)((((c) ^ ((r) & 7))) << 4))
// B swizzle: [K][N] rows of 256B (128 n x 2B); chunk = n>>3 (0..15)
#define BSWZ(k, n) ((uint32_t)((k) * 256 + (((((n) >> 3) ^ ((k) & 7))) << 4) + (((n) & 7) * 2)))

// ---------------- device scratch ----------------
__device__ unsigned short g_xah[(size_t)SLOTS * DT];   // fp16 hi plane of gathered x
__device__ unsigned short g_xal[(size_t)SLOTS * DT];   // fp16 lo plane
__device__ unsigned short g_hh[(size_t)SLOTS * FT];    // fp16 hi plane of h
__device__ unsigned short g_hl[(size_t)SLOTS * FT];    // fp16 lo plane

__device__ int   g_perm[SLOTS];
__device__ float g_pw[SLOTS];
__device__ int   g_topk_e[TT * KSEL];
__device__ float g_topk_w[TT * KSEL];
__device__ int   g_counts[ET];
__device__ int   g_cursor[ET];
__device__ int   g_padoff[ET];
__device__ int   g_tile_e[MAXT];
__device__ int   g_tile_r0[MAXT];
__device__ int   g_ntiles;

// ---------------- helpers ----------------
__device__ __forceinline__ uint32_t s2u(const void* p) {
    uint32_t a;
    asm("{ .reg .u64 t; cvta.to.shared.u64 t, %1; cvt.u32.u64 %0, t; }" : "=r"(a) : "l"(p));
    return a;
}
__device__ __forceinline__ void cpasync16(uint32_t dst, const void* src) {
    asm volatile("cp.async.cg.shared.global [%0], [%1], 16;" :: "r"(dst), "l"(src));
}
#define CP_COMMIT() asm volatile("cp.async.commit_group;" ::: "memory")
#define CP_WAIT1()  asm volatile("cp.async.wait_group 1;" ::: "memory")
#define CP_WAIT0()  asm volatile("cp.async.wait_group 0;" ::: "memory")

__device__ __forceinline__ void ldsm4(uint32_t* r, uint32_t a) {
    asm volatile("ldmatrix.sync.aligned.m8n8.x4.shared.b16 {%0,%1,%2,%3}, [%4];"
                 : "=r"(r[0]), "=r"(r[1]), "=r"(r[2]), "=r"(r[3]) : "r"(a));
}
__device__ __forceinline__ void ldsm4t(uint32_t* r, uint32_t a) {
    asm volatile("ldmatrix.sync.aligned.m8n8.x4.trans.shared.b16 {%0,%1,%2,%3}, [%4];"
                 : "=r"(r[0]), "=r"(r[1]), "=r"(r[2]), "=r"(r[3]) : "r"(a));
}
__device__ __forceinline__ void mma16816(float* c, const uint32_t* a, const uint32_t* b) {
    asm volatile("mma.sync.aligned.m16n8k16.row.col.f32.f16.f16.f32 "
                 "{%0,%1,%2,%3}, {%4,%5,%6,%7}, {%8,%9}, {%0,%1,%2,%3};"
                 : "+f"(c[0]), "+f"(c[1]), "+f"(c[2]), "+f"(c[3])
                 : "r"(a[0]), "r"(a[1]), "r"(a[2]), "r"(a[3]), "r"(b[0]), "r"(b[1]));
}
__device__ __forceinline__ void sts64(uint32_t a, uint32_t x, uint32_t y) {
    asm volatile("st.shared.v2.b32 [%0], {%1,%2};" :: "r"(a), "r"(x), "r"(y) : "memory");
}
// pack two floats into f16x2 (f0 -> lo16, f1 -> hi16)
__device__ __forceinline__ uint32_t packh2(float f0, float f1) {
    uint32_t d;
    asm("cvt.rn.f16x2.f32 %0, %1, %2;" : "=r"(d) : "f"(f1), "f"(f0));
    return d;
}
// fp16 hi/lo split of 4 floats
__device__ __forceinline__ void splitA4(const float4 v, uint32_t* hp, uint32_t* lp) {
    hp[0] = packh2(v.x, v.y);
    hp[1] = packh2(v.z, v.w);
    __half2 h01 = *(__half2*)&hp[0];
    __half2 h23 = *(__half2*)&hp[1];
    float2 b01 = __half22float2(h01);
    float2 b23 = __half22float2(h23);
    lp[0] = packh2(v.x - b01.x, v.y - b01.y);
    lp[1] = packh2(v.z - b23.x, v.w - b23.y);
}

// ---------------- stage 0: init ----------------
__global__ void init_kernel() {
    int i = blockIdx.x * blockDim.x + threadIdx.x;
    if (i < SLOTS) g_perm[i] = -1;
    if (i < ET) { g_counts[i] = 0; g_cursor[i] = 0; }
}

// ---------------- stage 1: gating ----------------
__global__ void gate_kernel(const float* __restrict__ x, const float* __restrict__ gw) {
    int gwarp = (blockIdx.x * blockDim.x + threadIdx.x) >> 5;
    int lane = threadIdx.x & 31;
    if (gwarp >= TT) return;
    const float* xr = x + (size_t)gwarp * DT;
    float acc[ET];
#pragma unroll
    for (int e = 0; e < ET; e++) acc[e] = 0.f;
    for (int i = lane; i < DT; i += 32) {
        float xv = xr[i];
        const float* g = gw + (size_t)i * ET;
#pragma unroll
        for (int e = 0; e < ET; e++) acc[e] += xv * g[e];
    }
#pragma unroll
    for (int e = 0; e < ET; e++)
#pragma unroll
        for (int o = 16; o; o >>= 1)
            acc[e] += __shfl_xor_sync(0xFFFFFFFFu, acc[e], o);
    if (lane == 0) {
        int i0 = 0; float v0 = acc[0];
#pragma unroll
        for (int e = 1; e < ET; e++) if (acc[e] > v0) { v0 = acc[e]; i0 = e; }
        int i1 = -1; float v1 = -3.4e38f;
#pragma unroll
        for (int e = 0; e < ET; e++) if (e != i0 && acc[e] > v1) { v1 = acc[e]; i1 = e; }
        float e1 = expf(v1 - v0);
        float inv = 1.0f / (1.0f + e1);
        int b = gwarp * KSEL;
        g_topk_e[b] = i0;     g_topk_w[b] = inv;
        g_topk_e[b + 1] = i1; g_topk_w[b + 1] = e1 * inv;
        atomicAdd(&g_counts[i0], 1);
        atomicAdd(&g_counts[i1], 1);
    }
}

// ---------------- stage 2: plan ----------------
__global__ void plan_kernel() {
    if (threadIdx.x != 0 || blockIdx.x != 0) return;
    int off = 0, tile = 0;
    for (int e = 0; e < ET; e++) {
        g_padoff[e] = off;
        int c = g_counts[e];
        int nt = (c + BM - 1) / BM;
        for (int t = 0; t < nt; t++) {
            g_tile_e[tile] = e;
            g_tile_r0[tile] = off + t * BM;
            tile++;
        }
        off += nt * BM;
    }
    g_ntiles = tile;
}

// ---------------- stage 3: scatter ----------------
__global__ void scatter_kernel() {
    int a = blockIdx.x * blockDim.x + threadIdx.x;
    if (a >= TT * KSEL) return;
    int e = g_topk_e[a];
    int pos = atomicAdd(&g_cursor[e], 1);
    int slot = g_padoff[e] + pos;
    g_perm[slot] = a >> 1;
    g_pw[slot] = g_topk_w[a];
}

// ---------------- stage 4: gather + fp16-split x ----------------
__global__ void convert_x_kernel(const float* __restrict__ x) {
    int slot = blockIdx.x;
    int t = threadIdx.x;
    int tok = g_perm[slot];
    float4 v = make_float4(0.f, 0.f, 0.f, 0.f);
    if (tok >= 0) v = ((const float4*)(x + (size_t)tok * DT))[t];
    uint32_t hp[2], lp[2];
    splitA4(v, hp, lp);
    ((uint2*)g_xah)[(size_t)slot * (DT / 4) + t] = make_uint2(hp[0], hp[1]);
    ((uint2*)g_xal)[(size_t)slot * (DT / 4) + t] = make_uint2(lp[0], lp[1]);
}

// ---------------- shared GEMM machinery ----------------
// A: 128 rows x 64 fp16 (hi & lo planes): 2048 16B chunks, 8 per thread
#define ISSUE_A(s) do {                                                  \
    uint32_t bb = sb + ((s) % 3) * STG_BYTES;                            \
    size_t ko = (size_t)(s) * 64;                                        \
    _Pragma("unroll")                                                    \
    for (int j = 0; j < 8; j++) cpasync16(bb + dstA[j], srcA[j] + ko * 2); \
    CP_COMMIT();                                                         \
} while (0)

// B: 64 k-rows x 128 n fp32 -> 8 float4 per thread
#define LDG_B(s) do {                                                    \
    _Pragma("unroll")                                                    \
    for (int j = 0; j < 8; j++)                                          \
        br[j] = *(const float4*)(srcB0 + (size_t)j * bstride             \
                                 + (size_t)(s) * 64 * bstride);          \
} while (0)

#define STS_B(s) do {                                                    \
    uint32_t bb = sb + ((s) % 3) * STG_BYTES;                            \
    _Pragma("unroll")                                                    \
    for (int j = 0; j < 8; j++) {                                        \
        uint32_t p0 = packh2(br[j].x, br[j].y);                          \
        uint32_t p1 = packh2(br[j].z, br[j].w);                          \
        sts64(bb + OFF_B + BSWZ(wid * 8 + j, bn), p0, p1);               \
    }                                                                    \
} while (0)

#define GEMM_MAINLOOP(KS) do {                                           \
    ISSUE_A(0);                                                          \
    ISSUE_A(1);                                                          \
    LDG_B(0);                                                            \
    for (int s = 0; s < (KS); s++) {                                     \
        CP_WAIT1();                                                      \
        STS_B(s);                                                        \
        __syncthreads();                                                 \
        if (s + 1 < (KS)) LDG_B(s + 1);                                  \
        if (s + 2 < (KS)) ISSUE_A(s + 2);                                \
        uint32_t b = sb + (s % 3) * STG_BYTES;                           \
        _Pragma("unroll")                                                \
        for (int ks = 0; ks < 4; ks++) {                                 \
            uint32_t ah[4][4], al[4][4], bhf[4][2];                      \
            int rr = lane & 15;                                          \
            int ch = 2 * ks + (lane >> 4);                               \
            _Pragma("unroll")                                            \
            for (int mf = 0; mf < 4; mf++) {                             \
                int r = wm * 64 + mf * 16 + rr;                          \
                uint32_t ad = b + r * 128 + SWZ(r, ch);                  \
                ldsm4(ah[mf], ad + OFF_A_H);                             \
                ldsm4(al[mf], ad + OFF_A_L);                             \
            }                                                            \
            {                                                            \
                int mat = lane >> 3, li = lane & 7;                      \
                int kk = ks * 16 + ((mat & 1) << 3) + li;                \
                _Pragma("unroll")                                        \
                for (int bi = 0; bi < 2; bi++) {                         \
                    int nn = wn * 32 + bi * 16 + ((mat >> 1) << 3);      \
                    uint32_t t4[4];                                      \
                    ldsm4t(t4, b + OFF_B + BSWZ(kk, nn));                \
                    bhf[bi*2+0][0] = t4[0]; bhf[bi*2+0][1] = t4[1];      \
                    bhf[bi*2+1][0] = t4[2]; bhf[bi*2+1][1] = t4[3];      \
                }                                                        \
            }                                                            \
            _Pragma("unroll")                                            \
            for (int mf = 0; mf < 4; mf++)                               \
                _Pragma("unroll")                                        \
                for (int nf = 0; nf < 4; nf++) {                         \
                    mma16816(cf[mf][nf], ah[mf], bhf[nf]);               \
                    mma16816(cf[mf][nf], al[mf], bhf[nf]);               \
                }                                                        \
        }                                                                \
    }                                                                    \
    CP_WAIT0();                                                          \
    __syncthreads();                                                     \
} while (0)

#define STORE_C_SMEM() do {                                              \
    float* Cs = (float*)dynsm;                                           \
    int g = lane >> 2, t4i = lane & 3;                                   \
    _Pragma("unroll")                                                    \
    for (int mf = 0; mf < 4; mf++)                                       \
        _Pragma("unroll")                                                \
        for (int nf = 0; nf < 4; nf++) {                                 \
            int m0 = wm * 64 + mf * 16 + g;                              \
            int n0 = wn * 32 + nf * 8 + 2 * t4i;                         \
            Cs[m0 * 132 + n0]           = cf[mf][nf][0];                 \
            Cs[m0 * 132 + n0 + 1]       = cf[mf][nf][1];                 \
            Cs[(m0 + 8) * 132 + n0]     = cf[mf][nf][2];                 \
            Cs[(m0 + 8) * 132 + n0 + 1] = cf[mf][nf][3];                 \
        }                                                                \
} while (0)

// ---------------- stage 5: GEMM1  h = silu(x@wi0) * (x@wi1) ----------------
__global__ __launch_bounds__(256, 1) void gemm1_kernel(
        const float* __restrict__ wi0, const float* __restrict__ wi1) {
    extern __shared__ char dynsm[];
    int tile = blockIdx.y;
    if (tile >= g_ntiles) return;
    int e = g_tile_e[tile];
    int row0 = g_tile_r0[tile];
    int f0 = blockIdx.x * 64;

    int tid = threadIdx.x;
    int lane = tid & 31;
    int wid = tid >> 5;
    int wm = wid >> 2, wn = wid & 3;
    uint32_t sb = s2u(dynsm);

    const char* srcA[8];
    uint32_t dstA[8];
#pragma unroll
    for (int j = 0; j < 8; j++) {
        int id = tid + j * 256;
        int arr = id >> 10;
        int r = (id >> 3) & 127;
        int c = id & 7;
        dstA[j] = (uint32_t)(arr * 16384 + r * 128) + SWZ(r, c);
        const unsigned short* p = (arr == 0) ? (g_xah + (size_t)(row0 + r) * DT)
                                             : (g_xal + (size_t)(row0 + r) * DT);
        srcA[j] = (const char*)(p + c * 8);
    }

    const int bstride = FT;
    int half = lane >> 4;
    int bn = half * 64 + (lane & 15) * 4;
    const float* srcB0 = ((half ? wi1 : wi0) + (size_t)e * DT * FT + f0 + (lane & 15) * 4)
                         + (size_t)(wid * 8) * FT;
    float4 br[8];

    float cf[4][4][4];
#pragma unroll
    for (int a = 0; a < 4; a++)
#pragma unroll
        for (int b2 = 0; b2 < 4; b2++)
#pragma unroll
            for (int c = 0; c < 4; c++) cf[a][b2][c] = 0.f;

    GEMM_MAINLOOP(DT / BK);

    STORE_C_SMEM();
    __syncthreads();

    const float* Cs = (const float*)dynsm;
#pragma unroll
    for (int i = 0; i < 8; i++) {
        int pos = tid + i * 256;
        int m = pos >> 4;
        int f = (pos & 15) * 4;
        float hv[4];
#pragma unroll
        for (int u = 0; u < 4; u++) {
            float d0 = Cs[m * 132 + f + u];
            float d1 = Cs[m * 132 + 64 + f + u];
            hv[u] = (d0 / (1.0f + __expf(-d0))) * d1;
        }
        float4 v = make_float4(hv[0], hv[1], hv[2], hv[3]);
        uint32_t hp[2], lp[2];
        splitA4(v, hp, lp);
        size_t o = (size_t)(row0 + m) * FT + f0 + f;
        *(uint2*)(g_hh + o) = make_uint2(hp[0], hp[1]);
        *(uint2*)(g_hl + o) = make_uint2(lp[0], lp[1]);
    }
}

// ---------------- stage 6: GEMM2  out[tok] += w * (h @ wo[e]) ----------------
__global__ __launch_bounds__(256, 1) void gemm2_kernel(
        const float* __restrict__ wo, float* __restrict__ out) {
    extern __shared__ char dynsm[];
    int tile = blockIdx.y;
    if (tile >= g_ntiles) return;
    int e = g_tile_e[tile];
    int row0 = g_tile_r0[tile];
    int d0 = blockIdx.x * 128;

    int tid = threadIdx.x;
    int lane = tid & 31;
    int wid = tid >> 5;
    int wm = wid >> 2, wn = wid & 3;
    uint32_t sb = s2u(dynsm);

    const char* srcA[8];
    uint32_t dstA[8];
#pragma unroll
    for (int j = 0; j < 8; j++) {
        int id = tid + j * 256;
        int arr = id >> 10;
        int r = (id >> 3) & 127;
        int c = id & 7;
        dstA[j] = (uint32_t)(arr * 16384 + r * 128) + SWZ(r, c);
        const unsigned short* p = (arr == 0) ? (g_hh + (size_t)(row0 + r) * FT)
                                             : (g_hl + (size_t)(row0 + r) * FT);
        srcA[j] = (const char*)(p + c * 8);
    }

    const int bstride = DT;
    int bn = lane * 4;
    const float* srcB0 = (wo + (size_t)e * FT * DT + d0 + lane * 4)
                         + (size_t)(wid * 8) * DT;
    float4 br[8];

    float cf[4][4][4];
#pragma unroll
    for (int a = 0; a < 4; a++)
#pragma unroll
        for (int b2 = 0; b2 < 4; b2++)
#pragma unroll
            for (int c = 0; c < 4; c++) cf[a][b2][c] = 0.f;

    GEMM_MAINLOOP(FT / BK);

    STORE_C_SMEM();

    int* stok = (int*)(dynsm + 128 * 132 * 4);
    float* spw = (float*)(dynsm + 128 * 132 * 4 + 512);
    if (tid < 128) {
        stok[tid] = g_perm[row0 + tid];
        spw[tid] = g_pw[row0 + tid];
    }
    __syncthreads();

    const float* Cs = (const float*)dynsm;
#pragma unroll 8
    for (int i = 0; i < 64; i++) {
        int pos = tid + i * 256;
        int n = pos & 127, m = pos >> 7;
        int tok = stok[m];
        if (tok >= 0)
            atomicAdd(out + (size_t)tok * DT + d0 + n, Cs[m * 132 + n] * spw[m]);
    }
}

// ---------------- launch ----------------
extern "C" void kernel_launch(void* const* d_in, const int* in_sizes, int n_in,
                              void* d_out, int out_size) {
    const float* x   = (const float*)d_in[0];
    const float* gw  = (const float*)d_in[1];
    const float* wi0 = (const float*)d_in[2];
    const float* wi1 = (const float*)d_in[3];
    const float* wo  = (const float*)d_in[4];
    float* out = (float*)d_out;

    cudaFuncSetAttribute(gemm1_kernel, cudaFuncAttributeMaxDynamicSharedMemorySize, SMEM_SZ);
    cudaFuncSetAttribute(gemm2_kernel, cudaFuncAttributeMaxDynamicSharedMemorySize, SMEM_SZ);

    init_kernel<<<(SLOTS + 255) / 256, 256>>>();
    gate_kernel<<<TT / 8, 256>>>(x, gw);
    plan_kernel<<<1, 1>>>();
    scatter_kernel<<<(TT * KSEL + 255) / 256, 256>>>();
    convert_x_kernel<<<SLOTS, 256>>>(x);
    cudaMemsetAsync(d_out, 0, (size_t)out_size * sizeof(float), 0);
    gemm1_kernel<<<dim3(FT / 64, MAXT), 256, SMEM_SZ>>>(wi0, wi1);
    gemm2_kernel<<<dim3(DT / 128, MAXT), 256, SMEM_SZ>>>(wo, out);
}

// round 7
// speedup vs baseline: 4.8369x; 1.1024x over previous
#include <cuda_runtime.h>
#include <cuda_fp16.h>
#include <stdint.h>
#include <math.h>

// ---------------- problem constants ----------------
#define DT   1024
#define FT   4096
#define ET   8
#define TT   8192
#define KSEL 2

#define BM    128
#define SLOTS 17408
#define MAXT  136
#define BK    64

// ---- GEMM1 staging: Ah 16K | Al 16K | B 16K ----
#define STG1     49152
#define OFF1_AH  0
#define OFF1_AL  16384
#define OFF1_B   32768
#define SMEM1    147456
// ---- GEMM2 staging: A 16K | B 16K ----
#define STG2     32768
#define OFF2_A   0
#define OFF2_B   16384
#define SMEM2    98304

// A swizzle: 16B chunk c (0..7) within 128B row r
#define SWZ(r, c) ((uint32_t)((((c) ^ ((r) & 7))) << 4))
// B swizzle: [K][N] rows of 256B (128 n x 2B)
#define BSWZ(k, n) ((uint32_t)((k) * 256 + (((((n) >> 3) ^ ((k) & 7))) << 4) + (((n) & 7) * 2)))

// ---------------- device scratch ----------------
__device__ unsigned short g_xah[(size_t)SLOTS * DT];   // fp16 hi plane of gathered x
__device__ unsigned short g_xal[(size_t)SLOTS * DT];   // fp16 lo plane
__device__ unsigned short g_hh[(size_t)SLOTS * FT];    // fp16 h (single plane)

__device__ int   g_perm[SLOTS];
__device__ float g_pw[SLOTS];
__device__ int   g_topk_e[TT * KSEL];
__device__ float g_topk_w[TT * KSEL];
__device__ int   g_counts[ET];
__device__ int   g_cursor[ET];
__device__ int   g_padoff[ET];
__device__ int   g_tile_e[MAXT];
__device__ int   g_tile_r0[MAXT];
__device__ int   g_ntiles;

// ---------------- helpers ----------------
__device__ __forceinline__ uint32_t s2u(const void* p) {
    uint32_t a;
    asm("{ .reg .u64 t; cvta.to.shared.u64 t, %1; cvt.u32.u64 %0, t; }" : "=r"(a) : "l"(p));
    return a;
}
__device__ __forceinline__ void cpasync16(uint32_t dst, const void* src) {
    asm volatile("cp.async.cg.shared.global [%0], [%1], 16;" :: "r"(dst), "l"(src));
}
#define CP_COMMIT() asm volatile("cp.async.commit_group;" ::: "memory")
#define CP_WAIT1()  asm volatile("cp.async.wait_group 1;" ::: "memory")
#define CP_WAIT0()  asm volatile("cp.async.wait_group 0;" ::: "memory")

__device__ __forceinline__ void ldsm4(uint32_t* r, uint32_t a) {
    asm volatile("ldmatrix.sync.aligned.m8n8.x4.shared.b16 {%0,%1,%2,%3}, [%4];"
                 : "=r"(r[0]), "=r"(r[1]), "=r"(r[2]), "=r"(r[3]) : "r"(a));
}
__device__ __forceinline__ void ldsm4t(uint32_t* r, uint32_t a) {
    asm volatile("ldmatrix.sync.aligned.m8n8.x4.trans.shared.b16 {%0,%1,%2,%3}, [%4];"
                 : "=r"(r[0]), "=r"(r[1]), "=r"(r[2]), "=r"(r[3]) : "r"(a));
}
__device__ __forceinline__ void mma16816(float* c, const uint32_t* a, const uint32_t* b) {
    asm volatile("mma.sync.aligned.m16n8k16.row.col.f32.f16.f16.f32 "
                 "{%0,%1,%2,%3}, {%4,%5,%6,%7}, {%8,%9}, {%0,%1,%2,%3};"
                 : "+f"(c[0]), "+f"(c[1]), "+f"(c[2]), "+f"(c[3])
                 : "r"(a[0]), "r"(a[1]), "r"(a[2]), "r"(a[3]), "r"(b[0]), "r"(b[1]));
}
__device__ __forceinline__ void sts64(uint32_t a, uint32_t x, uint32_t y) {
    asm volatile("st.shared.v2.b32 [%0], {%1,%2};" :: "r"(a), "r"(x), "r"(y) : "memory");
}
__device__ __forceinline__ uint32_t packh2(float f0, float f1) {
    uint32_t d;
    asm("cvt.rn.f16x2.f32 %0, %1, %2;" : "=r"(d) : "f"(f1), "f"(f0));
    return d;
}
__device__ __forceinline__ void splitA4(const float4 v, uint32_t* hp, uint32_t* lp) {
    hp[0] = packh2(v.x, v.y);
    hp[1] = packh2(v.z, v.w);
    __half2 h01 = *(__half2*)&hp[0];
    __half2 h23 = *(__half2*)&hp[1];
    float2 b01 = __half22float2(h01);
    float2 b23 = __half22float2(h23);
    lp[0] = packh2(v.x - b01.x, v.y - b01.y);
    lp[1] = packh2(v.z - b23.x, v.w - b23.y);
}

// ---------------- stage 0: init ----------------
__global__ void init_kernel() {
    int i = blockIdx.x * blockDim.x + threadIdx.x;
    if (i < SLOTS) g_perm[i] = -1;
    if (i < ET) { g_counts[i] = 0; g_cursor[i] = 0; }
}

// ---------------- stage 1: gating ----------------
__global__ void gate_kernel(const float* __restrict__ x, const float* __restrict__ gw) {
    int gwarp = (blockIdx.x * blockDim.x + threadIdx.x) >> 5;
    int lane = threadIdx.x & 31;
    if (gwarp >= TT) return;
    const float* xr = x + (size_t)gwarp * DT;
    float acc[ET];
#pragma unroll
    for (int e = 0; e < ET; e++) acc[e] = 0.f;
    for (int i = lane; i < DT; i += 32) {
        float xv = xr[i];
        const float* g = gw + (size_t)i * ET;
#pragma unroll
        for (int e = 0; e < ET; e++) acc[e] += xv * g[e];
    }
#pragma unroll
    for (int e = 0; e < ET; e++)
#pragma unroll
        for (int o = 16; o; o >>= 1)
            acc[e] += __shfl_xor_sync(0xFFFFFFFFu, acc[e], o);
    if (lane == 0) {
        int i0 = 0; float v0 = acc[0];
#pragma unroll
        for (int e = 1; e < ET; e++) if (acc[e] > v0) { v0 = acc[e]; i0 = e; }
        int i1 = -1; float v1 = -3.4e38f;
#pragma unroll
        for (int e = 0; e < ET; e++) if (e != i0 && acc[e] > v1) { v1 = acc[e]; i1 = e; }
        float e1 = expf(v1 - v0);
        float inv = 1.0f / (1.0f + e1);
        int b = gwarp * KSEL;
        g_topk_e[b] = i0;     g_topk_w[b] = inv;
        g_topk_e[b + 1] = i1; g_topk_w[b + 1] = e1 * inv;
        atomicAdd(&g_counts[i0], 1);
        atomicAdd(&g_counts[i1], 1);
    }
}

// ---------------- stage 2: plan ----------------
__global__ void plan_kernel() {
    if (threadIdx.x != 0 || blockIdx.x != 0) return;
    int off = 0, tile = 0;
    for (int e = 0; e < ET; e++) {
        g_padoff[e] = off;
        int c = g_counts[e];
        int nt = (c + BM - 1) / BM;
        for (int t = 0; t < nt; t++) {
            g_tile_e[tile] = e;
            g_tile_r0[tile] = off + t * BM;
            tile++;
        }
        off += nt * BM;
    }
    g_ntiles = tile;
}

// ---------------- stage 3: scatter ----------------
__global__ void scatter_kernel() {
    int a = blockIdx.x * blockDim.x + threadIdx.x;
    if (a >= TT * KSEL) return;
    int e = g_topk_e[a];
    int pos = atomicAdd(&g_cursor[e], 1);
    int slot = g_padoff[e] + pos;
    g_perm[slot] = a >> 1;
    g_pw[slot] = g_topk_w[a];
}

// ---------------- stage 4: gather + fp16-split x ----------------
__global__ void convert_x_kernel(const float* __restrict__ x) {
    int slot = blockIdx.x;
    int t = threadIdx.x;
    int tok = g_perm[slot];
    float4 v = make_float4(0.f, 0.f, 0.f, 0.f);
    if (tok >= 0) v = ((const float4*)(x + (size_t)tok * DT))[t];
    uint32_t hp[2], lp[2];
    splitA4(v, hp, lp);
    ((uint2*)g_xah)[(size_t)slot * (DT / 4) + t] = make_uint2(hp[0], hp[1]);
    ((uint2*)g_xal)[(size_t)slot * (DT / 4) + t] = make_uint2(lp[0], lp[1]);
}

// ---------------- GEMM1 machinery (A split 2-plane) ----------------
#define ISSUE_A1(s) do {                                                 \
    uint32_t bb = sb + ((s) % 3) * STG1;                                 \
    size_t ko = (size_t)(s) * 64;                                        \
    _Pragma("unroll")                                                    \
    for (int j = 0; j < 8; j++) cpasync16(bb + dstA[j], srcA[j] + ko * 2); \
    CP_COMMIT();                                                         \
} while (0)

#define LDG_B(s) do {                                                    \
    _Pragma("unroll")                                                    \
    for (int j = 0; j < 8; j++)                                          \
        br[j] = *(const float4*)(srcB0 + (size_t)j * bstride             \
                                 + (size_t)(s) * 64 * bstride);          \
} while (0)

#define STS_B1(s) do {                                                   \
    uint32_t bb = sb + ((s) % 3) * STG1;                                 \
    _Pragma("unroll")                                                    \
    for (int j = 0; j < 8; j++) {                                        \
        uint32_t p0 = packh2(br[j].x, br[j].y);                          \
        uint32_t p1 = packh2(br[j].z, br[j].w);                          \
        sts64(bb + OFF1_B + BSWZ(wid * 8 + j, bn), p0, p1);              \
    }                                                                    \
} while (0)

#define GEMM1_MAINLOOP(KS) do {                                          \
    ISSUE_A1(0);                                                         \
    ISSUE_A1(1);                                                         \
    LDG_B(0);                                                            \
    for (int s = 0; s < (KS); s++) {                                     \
        CP_WAIT1();                                                      \
        STS_B1(s);                                                       \
        __syncthreads();                                                 \
        if (s + 1 < (KS)) LDG_B(s + 1);                                  \
        if (s + 2 < (KS)) ISSUE_A1(s + 2);                               \
        uint32_t b = sb + (s % 3) * STG1;                                \
        _Pragma("unroll")                                                \
        for (int ks = 0; ks < 4; ks++) {                                 \
            uint32_t ah[4][4], al[4][4], bhf[4][2];                      \
            int rr = lane & 15;                                          \
            int ch = 2 * ks + (lane >> 4);                               \
            _Pragma("unroll")                                            \
            for (int mf = 0; mf < 4; mf++) {                             \
                int r = wm * 64 + mf * 16 + rr;                          \
                uint32_t ad = b + r * 128 + SWZ(r, ch);                  \
                ldsm4(ah[mf], ad + OFF1_AH);                             \
                ldsm4(al[mf], ad + OFF1_AL);                             \
            }                                                            \
            {                                                            \
                int mat = lane >> 3, li = lane & 7;                      \
                int kk = ks * 16 + ((mat & 1) << 3) + li;                \
                _Pragma("unroll")                                        \
                for (int bi = 0; bi < 2; bi++) {                         \
                    int nn = wn * 32 + bi * 16 + ((mat >> 1) << 3);      \
                    uint32_t t4[4];                                      \
                    ldsm4t(t4, b + OFF1_B + BSWZ(kk, nn));               \
                    bhf[bi*2+0][0] = t4[0]; bhf[bi*2+0][1] = t4[1];      \
                    bhf[bi*2+1][0] = t4[2]; bhf[bi*2+1][1] = t4[3];      \
                }                                                        \
            }                                                            \
            _Pragma("unroll")                                            \
            for (int mf = 0; mf < 4; mf++)                               \
                _Pragma("unroll")                                        \
                for (int nf = 0; nf < 4; nf++) {                         \
                    mma16816(cf[mf][nf], ah[mf], bhf[nf]);               \
                    mma16816(cf[mf][nf], al[mf], bhf[nf]);               \
                }                                                        \
        }                                                                \
    }                                                                    \
    CP_WAIT0();                                                          \
    __syncthreads();                                                     \
} while (0)

// ---------------- GEMM2 machinery (A single plane) ----------------
#define ISSUE_A2(s) do {                                                 \
    uint32_t bb = sb + ((s) % 3) * STG2;                                 \
    size_t ko = (size_t)(s) * 64;                                        \
    _Pragma("unroll")                                                    \
    for (int j = 0; j < 4; j++) cpasync16(bb + dstA[j], srcA[j] + ko * 2); \
    CP_COMMIT();                                                         \
} while (0)

#define STS_B2(s) do {                                                   \
    uint32_t bb = sb + ((s) % 3) * STG2;                                 \
    _Pragma("unroll")                                                    \
    for (int j = 0; j < 8; j++) {                                        \
        uint32_t p0 = packh2(br[j].x, br[j].y);                          \
        uint32_t p1 = packh2(br[j].z, br[j].w);                          \
        sts64(bb + OFF2_B + BSWZ(wid * 8 + j, bn), p0, p1);              \
    }                                                                    \
} while (0)

#define GEMM2_MAINLOOP(KS) do {                                          \
    ISSUE_A2(0);                                                         \
    ISSUE_A2(1);                                                         \
    LDG_B(0);                                                            \
    for (int s = 0; s < (KS); s++) {                                     \
        CP_WAIT1();                                                      \
        STS_B2(s);                                                       \
        __syncthreads();                                                 \
        if (s + 1 < (KS)) LDG_B(s + 1);                                  \
        if (s + 2 < (KS)) ISSUE_A2(s + 2);                               \
        uint32_t b = sb + (s % 3) * STG2;                                \
        _Pragma("unroll")                                                \
        for (int ks = 0; ks < 4; ks++) {                                 \
            uint32_t ah[4][4], bhf[4][2];                                \
            int rr = lane & 15;                                          \
            int ch = 2 * ks + (lane >> 4);                               \
            _Pragma("unroll")                                            \
            for (int mf = 0; mf < 4; mf++) {                             \
                int r = wm * 64 + mf * 16 + rr;                          \
                ldsm4(ah[mf], b + OFF2_A + r * 128 + SWZ(r, ch));        \
            }                                                            \
            {                                                            \
                int mat = lane >> 3, li = lane & 7;                      \
                int kk = ks * 16 + ((mat & 1) << 3) + li;                \
                _Pragma("unroll")                                        \
                for (int bi = 0; bi < 2; bi++) {                         \
                    int nn = wn * 32 + bi * 16 + ((mat >> 1) << 3);      \
                    uint32_t t4[4];                                      \
                    ldsm4t(t4, b + OFF2_B + BSWZ(kk, nn));               \
                    bhf[bi*2+0][0] = t4[0]; bhf[bi*2+0][1] = t4[1];      \
                    bhf[bi*2+1][0] = t4[2]; bhf[bi*2+1][1] = t4[3];      \
                }                                                        \
            }                                                            \
            _Pragma("unroll")                                            \
            for (int mf = 0; mf < 4; mf++)                               \
                _Pragma("unroll")                                        \
                for (int nf = 0; nf < 4; nf++)                           \
                    mma16816(cf[mf][nf], ah[mf], bhf[nf]);               \
        }                                                                \
    }                                                                    \
    CP_WAIT0();                                                          \
    __syncthreads();                                                     \
} while (0)

#define STORE_C_SMEM() do {                                              \
    float* Cs = (float*)dynsm;                                           \
    int g = lane >> 2, t4i = lane & 3;                                   \
    _Pragma("unroll")                                                    \
    for (int mf = 0; mf < 4; mf++)                                       \
        _Pragma("unroll")                                                \
        for (int nf = 0; nf < 4; nf++) {                                 \
            int m0 = wm * 64 + mf * 16 + g;                              \
            int n0 = wn * 32 + nf * 8 + 2 * t4i;                         \
            Cs[m0 * 132 + n0]           = cf[mf][nf][0];                 \
            Cs[m0 * 132 + n0 + 1]       = cf[mf][nf][1];                 \
            Cs[(m0 + 8) * 132 + n0]     = cf[mf][nf][2];                 \
            Cs[(m0 + 8) * 132 + n0 + 1] = cf[mf][nf][3];                 \
        }                                                                \
} while (0)

// ---------------- stage 5: GEMM1  h = silu(x@wi0) * (x@wi1) ----------------
__global__ __launch_bounds__(256, 1) void gemm1_kernel(
        const float* __restrict__ wi0, const float* __restrict__ wi1) {
    extern __shared__ char dynsm[];
    // raster: group of 8 fblocks, fblock-fast within group, tiles next
    int bid = blockIdx.x;
    int group = bid / (8 * MAXT);
    int rem = bid - group * 8 * MAXT;
    int fb = group * 8 + (rem & 7);
    int tile = rem >> 3;
    if (tile >= g_ntiles) return;
    int e = g_tile_e[tile];
    int row0 = g_tile_r0[tile];
    int f0 = fb * 64;

    int tid = threadIdx.x;
    int lane = tid & 31;
    int wid = tid >> 5;
    int wm = wid >> 2, wn = wid & 3;
    uint32_t sb = s2u(dynsm);

    const char* srcA[8];
    uint32_t dstA[8];
#pragma unroll
    for (int j = 0; j < 8; j++) {
        int id = tid + j * 256;
        int arr = id >> 10;
        int r = (id >> 3) & 127;
        int c = id & 7;
        dstA[j] = (uint32_t)(arr * 16384 + r * 128) + SWZ(r, c);
        const unsigned short* p = (arr == 0) ? (g_xah + (size_t)(row0 + r) * DT)
                                             : (g_xal + (size_t)(row0 + r) * DT);
        srcA[j] = (const char*)(p + c * 8);
    }

    const int bstride = FT;
    int half = lane >> 4;
    int bn = half * 64 + (lane & 15) * 4;
    const float* srcB0 = ((half ? wi1 : wi0) + (size_t)e * DT * FT + f0 + (lane & 15) * 4)
                         + (size_t)(wid * 8) * FT;
    float4 br[8];

    float cf[4][4][4];
#pragma unroll
    for (int a = 0; a < 4; a++)
#pragma unroll
        for (int b2 = 0; b2 < 4; b2++)
#pragma unroll
            for (int c = 0; c < 4; c++) cf[a][b2][c] = 0.f;

    GEMM1_MAINLOOP(DT / BK);

    STORE_C_SMEM();
    __syncthreads();

    const float* Cs = (const float*)dynsm;
#pragma unroll
    for (int i = 0; i < 8; i++) {
        int pos = tid + i * 256;
        int m = pos >> 4;
        int f = (pos & 15) * 4;
        float hv[4];
#pragma unroll
        for (int u = 0; u < 4; u++) {
            float d0 = Cs[m * 132 + f + u];
            float d1 = Cs[m * 132 + 64 + f + u];
            hv[u] = (d0 / (1.0f + __expf(-d0))) * d1;
        }
        uint32_t p0 = packh2(hv[0], hv[1]);
        uint32_t p1 = packh2(hv[2], hv[3]);
        size_t o = (size_t)(row0 + m) * FT + f0 + f;
        *(uint2*)(g_hh + o) = make_uint2(p0, p1);
    }
}

// ---------------- stage 6: GEMM2  out[tok] += w * (h @ wo[e]) ----------------
__global__ __launch_bounds__(256, 1) void gemm2_kernel(
        const float* __restrict__ wo, float* __restrict__ out) {
    extern __shared__ char dynsm[];
    int tile = blockIdx.y;
    if (tile >= g_ntiles) return;
    int e = g_tile_e[tile];
    int row0 = g_tile_r0[tile];
    int d0 = blockIdx.x * 128;

    int tid = threadIdx.x;
    int lane = tid & 31;
    int wid = tid >> 5;
    int wm = wid >> 2, wn = wid & 3;
    uint32_t sb = s2u(dynsm);

    const char* srcA[4];
    uint32_t dstA[4];
#pragma unroll
    for (int j = 0; j < 4; j++) {
        int id = tid + j * 256;
        int r = (id >> 3) & 127;
        int c = id & 7;
        dstA[j] = (uint32_t)(r * 128) + SWZ(r, c);
        srcA[j] = (const char*)(g_hh + (size_t)(row0 + r) * FT + c * 8);
    }

    const int bstride = DT;
    int bn = lane * 4;
    const float* srcB0 = (wo + (size_t)e * FT * DT + d0 + lane * 4)
                         + (size_t)(wid * 8) * DT;
    float4 br[8];

    float cf[4][4][4];
#pragma unroll
    for (int a = 0; a < 4; a++)
#pragma unroll
        for (int b2 = 0; b2 < 4; b2++)
#pragma unroll
            for (int c = 0; c < 4; c++) cf[a][b2][c] = 0.f;

    GEMM2_MAINLOOP(FT / BK);

    STORE_C_SMEM();

    int* stok = (int*)(dynsm + 128 * 132 * 4);
    float* spw = (float*)(dynsm + 128 * 132 * 4 + 512);
    if (tid < 128) {
        stok[tid] = g_perm[row0 + tid];
        spw[tid] = g_pw[row0 + tid];
    }
    __syncthreads();

    const float* Cs = (const float*)dynsm;
#pragma unroll 8
    for (int i = 0; i < 64; i++) {
        int pos = tid + i * 256;
        int n = pos & 127, m = pos >> 7;
        int tok = stok[m];
        if (tok >= 0)
            atomicAdd(out + (size_t)tok * DT + d0 + n, Cs[m * 132 + n] * spw[m]);
    }
}

// ---------------- launch ----------------
extern "C" void kernel_launch(void* const* d_in, const int* in_sizes, int n_in,
                              void* d_out, int out_size) {
    const float* x   = (const float*)d_in[0];
    const float* gw  = (const float*)d_in[1];
    const float* wi0 = (const float*)d_in[2];
    const float* wi1 = (const float*)d_in[3];
    const float* wo  = (const float*)d_in[4];
    float* out = (float*)d_out;

    cudaFuncSetAttribute(gemm1_kernel, cudaFuncAttributeMaxDynamicSharedMemorySize, SMEM1);
    cudaFuncSetAttribute(gemm2_kernel, cudaFuncAttributeMaxDynamicSharedMemorySize, SMEM2);

    init_kernel<<<(SLOTS + 255) / 256, 256>>>();
    gate_kernel<<<TT / 8, 256>>>(x, gw);
    plan_kernel<<<1, 1>>>();
    scatter_kernel<<<(TT * KSEL + 255) / 256, 256>>>();
    convert_x_kernel<<<SLOTS, 256>>>(x);
    cudaMemsetAsync(d_out, 0, (size_t)out_size * sizeof(float), 0);
    gemm1_kernel<<<64 * MAXT, 256, SMEM1>>>(wi0, wi1);
    gemm2_kernel<<<dim3(DT / 128, MAXT), 256, SMEM2>>>(wo, out);
}

// round 8
// speedup vs baseline: 7.0814x; 1.4641x over previous
#include <cuda_runtime.h>
#include <cuda_fp16.h>
#include <stdint.h>
#include <math.h>

// ---------------- problem constants ----------------
#define DT   1024
#define FT   4096
#define ET   8
#define TT   8192
#define KSEL 2

#define BM    128
#define SLOTS 17408
#define MAXT  136
#define BK    64

// ---- unified staging: A 16K | B 16K per stage, 3 stages ----
#define STG      32768
#define OFF_A    0
#define OFF_B    16384
#define SMEM_SZ  98304

// A swizzle: 16B chunk c (0..7) within 128B row r
#define SWZ(r, c) ((uint32_t)((((c) ^ ((r) & 7))) << 4))
// B swizzle: [K][N] rows of 256B (128 n x 2B)
#define BSWZ(k, n) ((uint32_t)((k) * 256 + (((((n) >> 3) ^ ((k) & 7))) << 4) + (((n) & 7) * 2)))

// ---------------- device scratch ----------------
__device__ unsigned short g_xah[(size_t)SLOTS * DT];   // fp16 gathered x
__device__ unsigned short g_hh[(size_t)SLOTS * FT];    // fp16 h

__device__ int   g_perm[SLOTS];
__device__ float g_pw[SLOTS];
__device__ int   g_topk_e[TT * KSEL];
__device__ float g_topk_w[TT * KSEL];
__device__ int   g_counts[ET];
__device__ int   g_cursor[ET];
__device__ int   g_padoff[ET];
__device__ int   g_tile_e[MAXT];
__device__ int   g_tile_r0[MAXT];
__device__ int   g_ntiles;
__device__ int   g_work1;
__device__ int   g_work2;

// ---------------- helpers ----------------
__device__ __forceinline__ uint32_t s2u(const void* p) {
    uint32_t a;
    asm("{ .reg .u64 t; cvta.to.shared.u64 t, %1; cvt.u32.u64 %0, t; }" : "=r"(a) : "l"(p));
    return a;
}
__device__ __forceinline__ void cpasync16(uint32_t dst, const void* src) {
    asm volatile("cp.async.cg.shared.global [%0], [%1], 16;" :: "r"(dst), "l"(src));
}
#define CP_COMMIT() asm volatile("cp.async.commit_group;" ::: "memory")
#define CP_WAIT1()  asm volatile("cp.async.wait_group 1;" ::: "memory")
#define CP_WAIT0()  asm volatile("cp.async.wait_group 0;" ::: "memory")

__device__ __forceinline__ void ldsm4(uint32_t* r, uint32_t a) {
    asm volatile("ldmatrix.sync.aligned.m8n8.x4.shared.b16 {%0,%1,%2,%3}, [%4];"
                 : "=r"(r[0]), "=r"(r[1]), "=r"(r[2]), "=r"(r[3]) : "r"(a));
}
__device__ __forceinline__ void ldsm4t(uint32_t* r, uint32_t a) {
    asm volatile("ldmatrix.sync.aligned.m8n8.x4.trans.shared.b16 {%0,%1,%2,%3}, [%4];"
                 : "=r"(r[0]), "=r"(r[1]), "=r"(r[2]), "=r"(r[3]) : "r"(a));
}
__device__ __forceinline__ void mma16816(float* c, const uint32_t* a, const uint32_t* b) {
    asm volatile("mma.sync.aligned.m16n8k16.row.col.f32.f16.f16.f32 "
                 "{%0,%1,%2,%3}, {%4,%5,%6,%7}, {%8,%9}, {%0,%1,%2,%3};"
                 : "+f"(c[0]), "+f"(c[1]), "+f"(c[2]), "+f"(c[3])
                 : "r"(a[0]), "r"(a[1]), "r"(a[2]), "r"(a[3]), "r"(b[0]), "r"(b[1]));
}
__device__ __forceinline__ void sts64(uint32_t a, uint32_t x, uint32_t y) {
    asm volatile("st.shared.v2.b32 [%0], {%1,%2};" :: "r"(a), "r"(x), "r"(y) : "memory");
}
__device__ __forceinline__ uint32_t packh2(float f0, float f1) {
    uint32_t d;
    asm("cvt.rn.f16x2.f32 %0, %1, %2;" : "=r"(d) : "f"(f1), "f"(f0));
    return d;
}

// ---------------- stage 0: init ----------------
__global__ void init_kernel() {
    int i = blockIdx.x * blockDim.x + threadIdx.x;
    if (i < SLOTS) g_perm[i] = -1;
    if (i < ET) { g_counts[i] = 0; g_cursor[i] = 0; }
    if (i == 0) { g_work1 = 0; g_work2 = 0; }
}

// ---------------- stage 1: gating ----------------
__global__ void gate_kernel(const float* __restrict__ x, const float* __restrict__ gw) {
    int gwarp = (blockIdx.x * blockDim.x + threadIdx.x) >> 5;
    int lane = threadIdx.x & 31;
    if (gwarp >= TT) return;
    const float* xr = x + (size_t)gwarp * DT;
    float acc[ET];
#pragma unroll
    for (int e = 0; e < ET; e++) acc[e] = 0.f;
    for (int i = lane; i < DT; i += 32) {
        float xv = xr[i];
        const float* g = gw + (size_t)i * ET;
#pragma unroll
        for (int e = 0; e < ET; e++) acc[e] += xv * g[e];
    }
#pragma unroll
    for (int e = 0; e < ET; e++)
#pragma unroll
        for (int o = 16; o; o >>= 1)
            acc[e] += __shfl_xor_sync(0xFFFFFFFFu, acc[e], o);
    if (lane == 0) {
        int i0 = 0; float v0 = acc[0];
#pragma unroll
        for (int e = 1; e < ET; e++) if (acc[e] > v0) { v0 = acc[e]; i0 = e; }
        int i1 = -1; float v1 = -3.4e38f;
#pragma unroll
        for (int e = 0; e < ET; e++) if (e != i0 && acc[e] > v1) { v1 = acc[e]; i1 = e; }
        float e1 = expf(v1 - v0);
        float inv = 1.0f / (1.0f + e1);
        int b = gwarp * KSEL;
        g_topk_e[b] = i0;     g_topk_w[b] = inv;
        g_topk_e[b + 1] = i1; g_topk_w[b + 1] = e1 * inv;
        atomicAdd(&g_counts[i0], 1);
        atomicAdd(&g_counts[i1], 1);
    }
}

// ---------------- stage 2: plan ----------------
__global__ void plan_kernel() {
    if (threadIdx.x != 0 || blockIdx.x != 0) return;
    int off = 0, tile = 0;
    for (int e = 0; e < ET; e++) {
        g_padoff[e] = off;
        int c = g_counts[e];
        int nt = (c + BM - 1) / BM;
        for (int t = 0; t < nt; t++) {
            g_tile_e[tile] = e;
            g_tile_r0[tile] = off + t * BM;
            tile++;
        }
        off += nt * BM;
    }
    g_ntiles = tile;
}

// ---------------- stage 3: scatter ----------------
__global__ void scatter_kernel() {
    int a = blockIdx.x * blockDim.x + threadIdx.x;
    if (a >= TT * KSEL) return;
    int e = g_topk_e[a];
    int pos = atomicAdd(&g_cursor[e], 1);
    int slot = g_padoff[e] + pos;
    g_perm[slot] = a >> 1;
    g_pw[slot] = g_topk_w[a];
}

// ---------------- stage 4: gather + fp16 x ----------------
__global__ void convert_x_kernel(const float* __restrict__ x) {
    int slot = blockIdx.x;
    int t = threadIdx.x;
    int tok = g_perm[slot];
    float4 v = make_float4(0.f, 0.f, 0.f, 0.f);
    if (tok >= 0) v = ((const float4*)(x + (size_t)tok * DT))[t];
    uint32_t p0 = packh2(v.x, v.y);
    uint32_t p1 = packh2(v.z, v.w);
    ((uint2*)g_xah)[(size_t)slot * (DT / 4) + t] = make_uint2(p0, p1);
}

// ---------------- shared GEMM machinery ----------------
// A: 128 rows x 64 fp16 = 1024 chunks of 16B, 4 per thread
#define ISSUE_A(s, KS) do {                                              \
    if ((s) < (KS)) {                                                    \
        uint32_t bb = sb + ((s) % 3) * STG;                              \
        size_t ko = (size_t)(s) * 128;                                   \
        _Pragma("unroll")                                                \
        for (int j = 0; j < 4; j++) cpasync16(bb + dstA[j], srcA[j] + ko); \
    }                                                                    \
    CP_COMMIT();                                                         \
} while (0)

// B: 64 k-rows x 128 n fp32 -> pack immediately to 16 u32
#define LDG_B(s) do {                                                    \
    _Pragma("unroll")                                                    \
    for (int j = 0; j < 8; j++) {                                        \
        float4 v = *(const float4*)(srcB0 + (size_t)j * bstride          \
                                    + (size_t)(s) * 64 * bstride);       \
        bp[2 * j]     = packh2(v.x, v.y);                                \
        bp[2 * j + 1] = packh2(v.z, v.w);                                \
    }                                                                    \
} while (0)

#define STS_B(s) do {                                                    \
    uint32_t bb = sb + ((s) % 3) * STG;                                  \
    _Pragma("unroll")                                                    \
    for (int j = 0; j < 8; j++)                                          \
        sts64(bb + OFF_B + BSWZ(wid * 8 + j, bn), bp[2 * j], bp[2 * j + 1]); \
} while (0)

#define GEMM_MAINLOOP(KS) do {                                           \
    ISSUE_A(0, KS);                                                      \
    ISSUE_A(1, KS);                                                      \
    LDG_B(0);                                                            \
    for (int s = 0; s < (KS); s++) {                                     \
        CP_WAIT1();                                                      \
        STS_B(s);                                                        \
        __syncthreads();                                                 \
        if (s + 1 < (KS)) LDG_B(s + 1);                                  \
        ISSUE_A(s + 2, KS);                                              \
        uint32_t b = sb + (s % 3) * STG;                                 \
        _Pragma("unroll")                                                \
        for (int ks = 0; ks < 4; ks++) {                                 \
            uint32_t ah[4][4], bhf[4][2];                                \
            int rr = lane & 15;                                          \
            int ch = 2 * ks + (lane >> 4);                               \
            _Pragma("unroll")                                            \
            for (int mf = 0; mf < 4; mf++) {                             \
                int r = wm * 64 + mf * 16 + rr;                          \
                ldsm4(ah[mf], b + OFF_A + r * 128 + SWZ(r, ch));         \
            }                                                            \
            {                                                            \
                int mat = lane >> 3, li = lane & 7;                      \
                int kk = ks * 16 + ((mat & 1) << 3) + li;                \
                _Pragma("unroll")                                        \
                for (int bi = 0; bi < 2; bi++) {                         \
                    int nn = wn * 32 + bi * 16 + ((mat >> 1) << 3);      \
                    uint32_t t4[4];                                      \
                    ldsm4t(t4, b + OFF_B + BSWZ(kk, nn));                \
                    bhf[bi*2+0][0] = t4[0]; bhf[bi*2+0][1] = t4[1];      \
                    bhf[bi*2+1][0] = t4[2]; bhf[bi*2+1][1] = t4[3];      \
                }                                                        \
            }                                                            \
            _Pragma("unroll")                                            \
            for (int mf = 0; mf < 4; mf++)                               \
                _Pragma("unroll")                                        \
                for (int nf = 0; nf < 4; nf++)                           \
                    mma16816(cf[mf][nf], ah[mf], bhf[nf]);               \
        }                                                                \
    }                                                                    \
    CP_WAIT0();                                                          \
    __syncthreads();                                                     \
} while (0)

#define STORE_C_SMEM() do {                                              \
    float* Cs = (float*)dynsm;                                           \
    int g = lane >> 2, t4i = lane & 3;                                   \
    _Pragma("unroll")                                                    \
    for (int mf = 0; mf < 4; mf++)                                       \
        _Pragma("unroll")                                                \
        for (int nf = 0; nf < 4; nf++) {                                 \
            int m0 = wm * 64 + mf * 16 + g;                              \
            int n0 = wn * 32 + nf * 8 + 2 * t4i;                         \
            Cs[m0 * 132 + n0]           = cf[mf][nf][0];                 \
            Cs[m0 * 132 + n0 + 1]       = cf[mf][nf][1];                 \
            Cs[(m0 + 8) * 132 + n0]     = cf[mf][nf][2];                 \
            Cs[(m0 + 8) * 132 + n0 + 1] = cf[mf][nf][3];                 \
        }                                                                \
} while (0)

// ---------------- stage 5: GEMM1 (persistent) ----------------
__global__ __launch_bounds__(256, 2) void gemm1_kernel(
        const float* __restrict__ wi0, const float* __restrict__ wi1) {
    extern __shared__ char dynsm[];
    __shared__ int s_item;
    int nt = g_ntiles;
    int total = nt * 64;
    int tid = threadIdx.x;
    int lane = tid & 31;
    int wid = tid >> 5;
    int wm = wid >> 2, wn = wid & 3;
    uint32_t sb = s2u(dynsm);

    // constant A-dst mapping
    uint32_t dstA[4];
    int arow[4], acol[4];
#pragma unroll
    for (int j = 0; j < 4; j++) {
        int id = tid + j * 256;
        arow[j] = (id >> 3) & 127;
        acol[j] = id & 7;
        dstA[j] = (uint32_t)(arow[j] * 128) + SWZ(arow[j], acol[j]);
    }

    const int bstride = FT;
    int half = lane >> 4;
    int bn = half * 64 + (lane & 15) * 4;

    for (;;) {
        if (tid == 0) s_item = atomicAdd(&g_work1, 1);
        __syncthreads();
        int item = s_item;
        if (item >= total) break;

        int group = item / (nt * 8);
        int rem = item - group * nt * 8;
        int fb = group * 8 + (rem & 7);
        int tile = rem >> 3;
        int e = g_tile_e[tile];
        int row0 = g_tile_r0[tile];
        int f0 = fb * 64;

        const char* srcA[4];
#pragma unroll
        for (int j = 0; j < 4; j++)
            srcA[j] = (const char*)(g_xah + (size_t)(row0 + arow[j]) * DT + acol[j] * 8);
        const float* srcB0 = ((half ? wi1 : wi0) + (size_t)e * DT * FT + f0 + (lane & 15) * 4)
                             + (size_t)(wid * 8) * FT;
        uint32_t bp[16];

        float cf[4][4][4];
#pragma unroll
        for (int a = 0; a < 4; a++)
#pragma unroll
            for (int b2 = 0; b2 < 4; b2++)
#pragma unroll
                for (int c = 0; c < 4; c++) cf[a][b2][c] = 0.f;

        GEMM_MAINLOOP(DT / BK);

        STORE_C_SMEM();
        __syncthreads();

        const float* Cs = (const float*)dynsm;
#pragma unroll
        for (int i = 0; i < 8; i++) {
            int pos = tid + i * 256;
            int m = pos >> 4;
            int f = (pos & 15) * 4;
            float hv[4];
#pragma unroll
            for (int u = 0; u < 4; u++) {
                float d0 = Cs[m * 132 + f + u];
                float d1 = Cs[m * 132 + 64 + f + u];
                hv[u] = (d0 / (1.0f + __expf(-d0))) * d1;
            }
            uint32_t p0 = packh2(hv[0], hv[1]);
            uint32_t p1 = packh2(hv[2], hv[3]);
            size_t o = (size_t)(row0 + m) * FT + f0 + f;
            *(uint2*)(g_hh + o) = make_uint2(p0, p1);
        }
        __syncthreads();
    }
}

// ---------------- stage 6: GEMM2 (persistent) ----------------
__global__ __launch_bounds__(256, 2) void gemm2_kernel(
        const float* __restrict__ wo, float* __restrict__ out) {
    extern __shared__ char dynsm[];
    __shared__ int s_item;
    int nt = g_ntiles;
    int total = nt * 8;
    int tid = threadIdx.x;
    int lane = tid & 31;
    int wid = tid >> 5;
    int wm = wid >> 2, wn = wid & 3;
    uint32_t sb = s2u(dynsm);

    uint32_t dstA[4];
    int arow[4], acol[4];
#pragma unroll
    for (int j = 0; j < 4; j++) {
        int id = tid + j * 256;
        arow[j] = (id >> 3) & 127;
        acol[j] = id & 7;
        dstA[j] = (uint32_t)(arow[j] * 128) + SWZ(arow[j], acol[j]);
    }

    const int bstride = DT;
    int bn = lane * 4;

    for (;;) {
        if (tid == 0) s_item = atomicAdd(&g_work2, 1);
        __syncthreads();
        int item = s_item;
        if (item >= total) break;

        int tile = item >> 3;
        int d0 = (item & 7) * 128;
        int e = g_tile_e[tile];
        int row0 = g_tile_r0[tile];

        const char* srcA[4];
#pragma unroll
        for (int j = 0; j < 4; j++)
            srcA[j] = (const char*)(g_hh + (size_t)(row0 + arow[j]) * FT + acol[j] * 8);
        const float* srcB0 = (wo + (size_t)e * FT * DT + d0 + lane * 4)
                             + (size_t)(wid * 8) * DT;
        uint32_t bp[16];

        float cf[4][4][4];
#pragma unroll
        for (int a = 0; a < 4; a++)
#pragma unroll
            for (int b2 = 0; b2 < 4; b2++)
#pragma unroll
                for (int c = 0; c < 4; c++) cf[a][b2][c] = 0.f;

        GEMM_MAINLOOP(FT / BK);

        STORE_C_SMEM();

        int* stok = (int*)(dynsm + 128 * 132 * 4);
        float* spw = (float*)(dynsm + 128 * 132 * 4 + 512);
        if (tid < 128) {
            stok[tid] = g_perm[row0 + tid];
            spw[tid] = g_pw[row0 + tid];
        }
        __syncthreads();

        const float* Cs = (const float*)dynsm;
#pragma unroll 8
        for (int i = 0; i < 64; i++) {
            int pos = tid + i * 256;
            int n = pos & 127, m = pos >> 7;
            int tok = stok[m];
            if (tok >= 0)
                atomicAdd(out + (size_t)tok * DT + d0 + n, Cs[m * 132 + n] * spw[m]);
        }
        __syncthreads();
    }
}

// ---------------- launch ----------------
extern "C" void kernel_launch(void* const* d_in, const int* in_sizes, int n_in,
                              void* d_out, int out_size) {
    const float* x   = (const float*)d_in[0];
    const float* gw  = (const float*)d_in[1];
    const float* wi0 = (const float*)d_in[2];
    const float* wi1 = (const float*)d_in[3];
    const float* wo  = (const float*)d_in[4];
    float* out = (float*)d_out;

    cudaFuncSetAttribute(gemm1_kernel, cudaFuncAttributeMaxDynamicSharedMemorySize, SMEM_SZ);
    cudaFuncSetAttribute(gemm2_kernel, cudaFuncAttributeMaxDynamicSharedMemorySize, SMEM_SZ);

    init_kernel<<<(SLOTS + 255) / 256, 256>>>();
    gate_kernel<<<TT / 8, 256>>>(x, gw);
    plan_kernel<<<1, 1>>>();
    scatter_kernel<<<(TT * KSEL + 255) / 256, 256>>>();
    convert_x_kernel<<<SLOTS, 256>>>(x);
    cudaMemsetAsync(d_out, 0, (size_t)out_size * sizeof(float), 0);
    gemm1_kernel<<<296, 256, SMEM_SZ>>>(wi0, wi1);
    gemm2_kernel<<<296, 256, SMEM_SZ>>>(wo, out);
}

// round 9
// speedup vs baseline: 7.0907x; 1.0013x over previous
#include <cuda_runtime.h>
#include <cuda_fp16.h>
#include <stdint.h>
#include <math.h>

// ---------------- problem constants ----------------
#define DT   1024
#define FT   4096
#define ET   8
#define TT   8192
#define KSEL 2

#define BM    128
#define SLOTS 17408
#define MAXT  136
#define BK    64

// ---- unified staging: A 16K | B 16K per stage, 3 stages ----
#define STG      32768
#define OFF_A    0
#define OFF_B    16384
#define SMEM_SZ  98304

// A swizzle: 16B chunk c (0..7) within 128B row r
#define SWZ(r, c) ((uint32_t)((((c) ^ ((r) & 7))) << 4))
// B swizzle: [K][N] rows of 256B (128 n x 2B)
#define BSWZ(k, n) ((uint32_t)((k) * 256 + (((((n) >> 3) ^ ((k) & 7))) << 4) + (((n) & 7) * 2)))

// ---------------- device scratch ----------------
__device__ unsigned short g_xah[(size_t)SLOTS * DT];   // fp16 gathered x
__device__ unsigned short g_hh[(size_t)SLOTS * FT];    // fp16 h
__device__ float g_cbuf[(size_t)2 * TT * DT];          // per-assignment-rank output

__device__ int   g_perm[SLOTS];
__device__ float g_pw[SLOTS];
__device__ unsigned char g_pk[SLOTS];                  // assignment rank (0/1)
__device__ int   g_topk_e[TT * KSEL];
__device__ float g_topk_w[TT * KSEL];
__device__ int   g_counts[ET];
__device__ int   g_cursor[ET];
__device__ int   g_padoff[ET];
__device__ int   g_tile_e[MAXT];
__device__ int   g_tile_r0[MAXT];
__device__ int   g_ntiles;
__device__ int   g_work1;
__device__ int   g_work2;

// ---------------- helpers ----------------
__device__ __forceinline__ uint32_t s2u(const void* p) {
    uint32_t a;
    asm("{ .reg .u64 t; cvta.to.shared.u64 t, %1; cvt.u32.u64 %0, t; }" : "=r"(a) : "l"(p));
    return a;
}
__device__ __forceinline__ void cpasync16(uint32_t dst, const void* src) {
    asm volatile("cp.async.cg.shared.global [%0], [%1], 16;" :: "r"(dst), "l"(src));
}
#define CP_COMMIT() asm volatile("cp.async.commit_group;" ::: "memory")
#define CP_WAIT1()  asm volatile("cp.async.wait_group 1;" ::: "memory")
#define CP_WAIT0()  asm volatile("cp.async.wait_group 0;" ::: "memory")

__device__ __forceinline__ void ldsm4(uint32_t* r, uint32_t a) {
    asm volatile("ldmatrix.sync.aligned.m8n8.x4.shared.b16 {%0,%1,%2,%3}, [%4];"
                 : "=r"(r[0]), "=r"(r[1]), "=r"(r[2]), "=r"(r[3]) : "r"(a));
}
__device__ __forceinline__ void ldsm4t(uint32_t* r, uint32_t a) {
    asm volatile("ldmatrix.sync.aligned.m8n8.x4.trans.shared.b16 {%0,%1,%2,%3}, [%4];"
                 : "=r"(r[0]), "=r"(r[1]), "=r"(r[2]), "=r"(r[3]) : "r"(a));
}
__device__ __forceinline__ void mma16816(float* c, const uint32_t* a, const uint32_t* b) {
    asm volatile("mma.sync.aligned.m16n8k16.row.col.f32.f16.f16.f32 "
                 "{%0,%1,%2,%3}, {%4,%5,%6,%7}, {%8,%9}, {%0,%1,%2,%3};"
                 : "+f"(c[0]), "+f"(c[1]), "+f"(c[2]), "+f"(c[3])
                 : "r"(a[0]), "r"(a[1]), "r"(a[2]), "r"(a[3]), "r"(b[0]), "r"(b[1]));
}
__device__ __forceinline__ void sts64(uint32_t a, uint32_t x, uint32_t y) {
    asm volatile("st.shared.v2.b32 [%0], {%1,%2};" :: "r"(a), "r"(x), "r"(y) : "memory");
}
__device__ __forceinline__ uint32_t packh2(float f0, float f1) {
    uint32_t d;
    asm("cvt.rn.f16x2.f32 %0, %1, %2;" : "=r"(d) : "f"(f1), "f"(f0));
    return d;
}

// ---------------- stage 0: init ----------------
__global__ void init_kernel() {
    int i = blockIdx.x * blockDim.x + threadIdx.x;
    if (i < SLOTS) g_perm[i] = -1;
    if (i < ET) { g_counts[i] = 0; g_cursor[i] = 0; }
    if (i == 0) { g_work1 = 0; g_work2 = 0; }
}

// ---------------- stage 1: gating ----------------
__global__ void gate_kernel(const float* __restrict__ x, const float* __restrict__ gw) {
    int gwarp = (blockIdx.x * blockDim.x + threadIdx.x) >> 5;
    int lane = threadIdx.x & 31;
    if (gwarp >= TT) return;
    const float* xr = x + (size_t)gwarp * DT;
    float acc[ET];
#pragma unroll
    for (int e = 0; e < ET; e++) acc[e] = 0.f;
    for (int i = lane; i < DT; i += 32) {
        float xv = xr[i];
        const float* g = gw + (size_t)i * ET;
#pragma unroll
        for (int e = 0; e < ET; e++) acc[e] += xv * g[e];
    }
#pragma unroll
    for (int e = 0; e < ET; e++)
#pragma unroll
        for (int o = 16; o; o >>= 1)
            acc[e] += __shfl_xor_sync(0xFFFFFFFFu, acc[e], o);
    if (lane == 0) {
        int i0 = 0; float v0 = acc[0];
#pragma unroll
        for (int e = 1; e < ET; e++) if (acc[e] > v0) { v0 = acc[e]; i0 = e; }
        int i1 = -1; float v1 = -3.4e38f;
#pragma unroll
        for (int e = 0; e < ET; e++) if (e != i0 && acc[e] > v1) { v1 = acc[e]; i1 = e; }
        float e1 = expf(v1 - v0);
        float inv = 1.0f / (1.0f + e1);
        int b = gwarp * KSEL;
        g_topk_e[b] = i0;     g_topk_w[b] = inv;
        g_topk_e[b + 1] = i1; g_topk_w[b + 1] = e1 * inv;
        atomicAdd(&g_counts[i0], 1);
        atomicAdd(&g_counts[i1], 1);
    }
}

// ---------------- stage 2: plan ----------------
__global__ void plan_kernel() {
    if (threadIdx.x != 0 || blockIdx.x != 0) return;
    int off = 0, tile = 0;
    for (int e = 0; e < ET; e++) {
        g_padoff[e] = off;
        int c = g_counts[e];
        int nt = (c + BM - 1) / BM;
        for (int t = 0; t < nt; t++) {
            g_tile_e[tile] = e;
            g_tile_r0[tile] = off + t * BM;
            tile++;
        }
        off += nt * BM;
    }
    g_ntiles = tile;
}

// ---------------- stage 3: scatter ----------------
__global__ void scatter_kernel() {
    int a = blockIdx.x * blockDim.x + threadIdx.x;
    if (a >= TT * KSEL) return;
    int e = g_topk_e[a];
    int pos = atomicAdd(&g_cursor[e], 1);
    int slot = g_padoff[e] + pos;
    g_perm[slot] = a >> 1;
    g_pw[slot] = g_topk_w[a];
    g_pk[slot] = (unsigned char)(a & 1);
}

// ---------------- stage 4: gather + fp16 x ----------------
__global__ void convert_x_kernel(const float* __restrict__ x) {
    int slot = blockIdx.x;
    int t = threadIdx.x;
    int tok = g_perm[slot];
    float4 v = make_float4(0.f, 0.f, 0.f, 0.f);
    if (tok >= 0) v = ((const float4*)(x + (size_t)tok * DT))[t];
    uint32_t p0 = packh2(v.x, v.y);
    uint32_t p1 = packh2(v.z, v.w);
    ((uint2*)g_xah)[(size_t)slot * (DT / 4) + t] = make_uint2(p0, p1);
}

// ---------------- shared GEMM machinery ----------------
#define ISSUE_A(s, KS) do {                                              \
    if ((s) < (KS)) {                                                    \
        uint32_t bb = sb + ((s) % 3) * STG;                              \
        size_t ko = (size_t)(s) * 128;                                   \
        _Pragma("unroll")                                                \
        for (int j = 0; j < 4; j++) cpasync16(bb + dstA[j], srcA[j] + ko); \
    }                                                                    \
    CP_COMMIT();                                                         \
} while (0)

#define LDG_B(s) do {                                                    \
    _Pragma("unroll")                                                    \
    for (int j = 0; j < 8; j++) {                                        \
        float4 v = *(const float4*)(srcB0 + (size_t)j * bstride          \
                                    + (size_t)(s) * 64 * bstride);       \
        bp[2 * j]     = packh2(v.x, v.y);                                \
        bp[2 * j + 1] = packh2(v.z, v.w);                                \
    }                                                                    \
} while (0)

#define STS_B(s) do {                                                    \
    uint32_t bb = sb + ((s) % 3) * STG;                                  \
    _Pragma("unroll")                                                    \
    for (int j = 0; j < 8; j++)                                          \
        sts64(bb + OFF_B + BSWZ(wid * 8 + j, bn), bp[2 * j], bp[2 * j + 1]); \
} while (0)

#define GEMM_MAINLOOP(KS) do {                                           \
    ISSUE_A(0, KS);                                                      \
    ISSUE_A(1, KS);                                                      \
    LDG_B(0);                                                            \
    for (int s = 0; s < (KS); s++) {                                     \
        CP_WAIT1();                                                      \
        STS_B(s);                                                        \
        __syncthreads();                                                 \
        if (s + 1 < (KS)) LDG_B(s + 1);                                  \
        ISSUE_A(s + 2, KS);                                              \
        uint32_t b = sb + (s % 3) * STG;                                 \
        _Pragma("unroll")                                                \
        for (int ks = 0; ks < 4; ks++) {                                 \
            uint32_t ah[4][4], bhf[4][2];                                \
            int rr = lane & 15;                                          \
            int ch = 2 * ks + (lane >> 4);                               \
            _Pragma("unroll")                                            \
            for (int mf = 0; mf < 4; mf++) {                             \
                int r = wm * 64 + mf * 16 + rr;                          \
                ldsm4(ah[mf], b + OFF_A + r * 128 + SWZ(r, ch));         \
            }                                                            \
            {                                                            \
                int mat = lane >> 3, li = lane & 7;                      \
                int kk = ks * 16 + ((mat & 1) << 3) + li;                \
                _Pragma("unroll")                                        \
                for (int bi = 0; bi < 2; bi++) {                         \
                    int nn = wn * 32 + bi * 16 + ((mat >> 1) << 3);      \
                    uint32_t t4[4];                                      \
                    ldsm4t(t4, b + OFF_B + BSWZ(kk, nn));                \
                    bhf[bi*2+0][0] = t4[0]; bhf[bi*2+0][1] = t4[1];      \
                    bhf[bi*2+1][0] = t4[2]; bhf[bi*2+1][1] = t4[3];      \
                }                                                        \
            }                                                            \
            _Pragma("unroll")                                            \
            for (int mf = 0; mf < 4; mf++)                               \
                _Pragma("unroll")                                        \
                for (int nf = 0; nf < 4; nf++)                           \
                    mma16816(cf[mf][nf], ah[mf], bhf[nf]);               \
        }                                                                \
    }                                                                    \
    CP_WAIT0();                                                          \
    __syncthreads();                                                     \
} while (0)

#define STORE_C_SMEM() do {                                              \
    float* Cs = (float*)dynsm;                                           \
    int g = lane >> 2, t4i = lane & 3;                                   \
    _Pragma("unroll")                                                    \
    for (int mf = 0; mf < 4; mf++)                                       \
        _Pragma("unroll")                                                \
        for (int nf = 0; nf < 4; nf++) {                                 \
            int m0 = wm * 64 + mf * 16 + g;                              \
            int n0 = wn * 32 + nf * 8 + 2 * t4i;                         \
            Cs[m0 * 132 + n0]           = cf[mf][nf][0];                 \
            Cs[m0 * 132 + n0 + 1]       = cf[mf][nf][1];                 \
            Cs[(m0 + 8) * 132 + n0]     = cf[mf][nf][2];                 \
            Cs[(m0 + 8) * 132 + n0 + 1] = cf[mf][nf][3];                 \
        }                                                                \
} while (0)

// ---------------- stage 5: GEMM1 (persistent) ----------------
__global__ __launch_bounds__(256, 2) void gemm1_kernel(
        const float* __restrict__ wi0, const float* __restrict__ wi1) {
    extern __shared__ char dynsm[];
    __shared__ int s_item;
    int nt = g_ntiles;
    int total = nt * 64;
    int tid = threadIdx.x;
    int lane = tid & 31;
    int wid = tid >> 5;
    int wm = wid >> 2, wn = wid & 3;
    uint32_t sb = s2u(dynsm);

    uint32_t dstA[4];
    int arow[4], acol[4];
#pragma unroll
    for (int j = 0; j < 4; j++) {
        int id = tid + j * 256;
        arow[j] = (id >> 3) & 127;
        acol[j] = id & 7;
        dstA[j] = (uint32_t)(arow[j] * 128) + SWZ(arow[j], acol[j]);
    }

    const int bstride = FT;
    int half = lane >> 4;
    int bn = half * 64 + (lane & 15) * 4;

    for (;;) {
        if (tid == 0) s_item = atomicAdd(&g_work1, 1);
        __syncthreads();
        int item = s_item;
        if (item >= total) break;

        int group = item / (nt * 8);
        int rem = item - group * nt * 8;
        int fb = group * 8 + (rem & 7);
        int tile = rem >> 3;
        int e = g_tile_e[tile];
        int row0 = g_tile_r0[tile];
        int f0 = fb * 64;

        const char* srcA[4];
#pragma unroll
        for (int j = 0; j < 4; j++)
            srcA[j] = (const char*)(g_xah + (size_t)(row0 + arow[j]) * DT + acol[j] * 8);
        const float* srcB0 = ((half ? wi1 : wi0) + (size_t)e * DT * FT + f0 + (lane & 15) * 4)
                             + (size_t)(wid * 8) * FT;
        uint32_t bp[16];

        float cf[4][4][4];
#pragma unroll
        for (int a = 0; a < 4; a++)
#pragma unroll
            for (int b2 = 0; b2 < 4; b2++)
#pragma unroll
                for (int c = 0; c < 4; c++) cf[a][b2][c] = 0.f;

        GEMM_MAINLOOP(DT / BK);

        STORE_C_SMEM();
        __syncthreads();

        const float* Cs = (const float*)dynsm;
#pragma unroll
        for (int i = 0; i < 8; i++) {
            int pos = tid + i * 256;
            int m = pos >> 4;
            int f = (pos & 15) * 4;
            float hv[4];
#pragma unroll
            for (int u = 0; u < 4; u++) {
                float d0 = Cs[m * 132 + f + u];
                float d1 = Cs[m * 132 + 64 + f + u];
                hv[u] = (d0 / (1.0f + __expf(-d0))) * d1;
            }
            uint32_t p0 = packh2(hv[0], hv[1]);
            uint32_t p1 = packh2(hv[2], hv[3]);
            size_t o = (size_t)(row0 + m) * FT + f0 + f;
            *(uint2*)(g_hh + o) = make_uint2(p0, p1);
        }
        __syncthreads();
    }
}

// ---------------- stage 6: GEMM2 (persistent, atomic-free epilogue) ----------------
__global__ __launch_bounds__(256, 2) void gemm2_kernel(
        const float* __restrict__ wo) {
    extern __shared__ char dynsm[];
    __shared__ int s_item;
    int nt = g_ntiles;
    int total = nt * 8;
    int tid = threadIdx.x;
    int lane = tid & 31;
    int wid = tid >> 5;
    int wm = wid >> 2, wn = wid & 3;
    uint32_t sb = s2u(dynsm);

    uint32_t dstA[4];
    int arow[4], acol[4];
#pragma unroll
    for (int j = 0; j < 4; j++) {
        int id = tid + j * 256;
        arow[j] = (id >> 3) & 127;
        acol[j] = id & 7;
        dstA[j] = (uint32_t)(arow[j] * 128) + SWZ(arow[j], acol[j]);
    }

    const int bstride = DT;
    int bn = lane * 4;

    for (;;) {
        if (tid == 0) s_item = atomicAdd(&g_work2, 1);
        __syncthreads();
        int item = s_item;
        if (item >= total) break;

        int tile = item >> 3;
        int d0 = (item & 7) * 128;
        int e = g_tile_e[tile];
        int row0 = g_tile_r0[tile];

        const char* srcA[4];
#pragma unroll
        for (int j = 0; j < 4; j++)
            srcA[j] = (const char*)(g_hh + (size_t)(row0 + arow[j]) * FT + acol[j] * 8);
        const float* srcB0 = (wo + (size_t)e * FT * DT + d0 + lane * 4)
                             + (size_t)(wid * 8) * DT;
        uint32_t bp[16];

        float cf[4][4][4];
#pragma unroll
        for (int a = 0; a < 4; a++)
#pragma unroll
            for (int b2 = 0; b2 < 4; b2++)
#pragma unroll
                for (int c = 0; c < 4; c++) cf[a][b2][c] = 0.f;

        GEMM_MAINLOOP(FT / BK);

        STORE_C_SMEM();

        int* stok = (int*)(dynsm + 128 * 132 * 4);
        float* spw = (float*)(dynsm + 128 * 132 * 4 + 512);
        int* spk = (int*)(dynsm + 128 * 132 * 4 + 1024);
        if (tid < 128) {
            stok[tid] = g_perm[row0 + tid];
            spw[tid] = g_pw[row0 + tid];
            spk[tid] = g_pk[row0 + tid];
        }
        __syncthreads();

        const float* Cs = (const float*)dynsm;
#pragma unroll 8
        for (int i = 0; i < 64; i++) {
            int pos = tid + i * 256;
            int n = pos & 127, m = pos >> 7;
            int tok = stok[m];
            if (tok >= 0)
                g_cbuf[(size_t)spk[m] * TT * DT + (size_t)tok * DT + d0 + n]
                    = Cs[m * 132 + n] * spw[m];
        }
        __syncthreads();
    }
}

// ---------------- stage 7: combine  out = c0 + c1 ----------------
__global__ void combine_kernel(float* __restrict__ out) {
    size_t i = (size_t)blockIdx.x * blockDim.x + threadIdx.x;
    float4 a = ((const float4*)g_cbuf)[i];
    float4 b = ((const float4*)(g_cbuf + (size_t)TT * DT))[i];
    float4 r;
    r.x = a.x + b.x; r.y = a.y + b.y; r.z = a.z + b.z; r.w = a.w + b.w;
    ((float4*)out)[i] = r;
}

// ---------------- launch ----------------
extern "C" void kernel_launch(void* const* d_in, const int* in_sizes, int n_in,
                              void* d_out, int out_size) {
    const float* x   = (const float*)d_in[0];
    const float* gw  = (const float*)d_in[1];
    const float* wi0 = (const float*)d_in[2];
    const float* wi1 = (const float*)d_in[3];
    const float* wo  = (const float*)d_in[4];
    float* out = (float*)d_out;

    cudaFuncSetAttribute(gemm1_kernel, cudaFuncAttributeMaxDynamicSharedMemorySize, SMEM_SZ);
    cudaFuncSetAttribute(gemm2_kernel, cudaFuncAttributeMaxDynamicSharedMemorySize, SMEM_SZ);

    init_kernel<<<(SLOTS + 255) / 256, 256>>>();
    gate_kernel<<<TT / 8, 256>>>(x, gw);
    plan_kernel<<<1, 1>>>();
    scatter_kernel<<<(TT * KSEL + 255) / 256, 256>>>();
    convert_x_kernel<<<SLOTS, 256>>>(x);
    gemm1_kernel<<<296, 256, SMEM_SZ>>>(wi0, wi1);
    gemm2_kernel<<<296, 256, SMEM_SZ>>>(wo);
    combine_kernel<<<(TT * DT / 4) / 256, 256>>>(out);
}